// round 2
// baseline (speedup 1.0000x reference)
#include <cuda_runtime.h>
#include <math.h>

#define NP 2048
#define NW 89
#define NA 2137
#define BB 16384
#define EE2 768
#define UWD 313
#define HH 8
#define FF 256
#define OO 32

// output layout: concat of flattened outputs in reference return order
#define OFF_O1N 0LL                 // (B,64)
#define OFF_O2N 1048576LL           // (B,64)
#define OFF_XT  2097152LL           // (B,5)
#define OFF_APP 2179072LL           // (8,2048,2048)
#define OFF_AWP 35733504LL          // (8,2137,2137)
#define OFF_X   72267656LL          // (B,256)

// -------- scratch (no allocations allowed -> device globals) --------
__device__ float g_hp1[HH*NP*OO];
__device__ float g_es1[HH*NP];
__device__ float g_ed1[HH*NP];
__device__ float g_h1wp[NA*FF];
__device__ float g_hp2[HH*NA*OO];
__device__ float g_es2[HH*NA];
__device__ float g_ed2[HH*NA];
__device__ float g_out2[HH*NW*OO];
__device__ float g_h2w[NW*OO];

// -------- copy word features into top of h1_wp --------
__global__ void k_copy_word(const float* __restrict__ wf){
    int i = blockIdx.x*blockDim.x + threadIdx.x;
    if (i < NW*FF) g_h1wp[i] = wf[i];
}

// -------- hp = einsum('nf,hfo->hno'), plus e_src/e_dst  --------
// GEMM view: (N x 256) @ (256 x 256[h*32+o]); 32 rows per block, 256 threads = 1 col each.
template<int SEL>
__global__ void __launch_bounds__(256) k_hp(const float* __restrict__ hin,
        const float* __restrict__ w, const float* __restrict__ asrc,
        const float* __restrict__ adst)
{
    constexpr int N = SEL ? NA : NP;
    const float* h  = SEL ? g_h1wp : hin;
    float* hp = SEL ? g_hp2 : g_hp1;
    float* es = SEL ? g_es2 : g_es1;
    float* ed = SEL ? g_ed2 : g_ed1;

    __shared__ float buf[64*36];
    const int b0 = blockIdx.x*32;
    const int tid = threadIdx.x;
    const int hd = tid>>5, o = tid&31;

    float acc[32];
    #pragma unroll
    for (int r=0;r<32;r++) acc[r]=0.f;

    for (int k0=0;k0<FF;k0+=64){
        __syncthreads();
        for (int i=tid;i<2048;i+=256){
            int r=i>>6, kk=i&63;
            int n=b0+r;
            buf[kk*36+r] = (n<N) ? h[(long long)n*FF + (k0+kk)] : 0.f;
        }
        __syncthreads();
        #pragma unroll 4
        for (int kk=0;kk<64;kk++){
            float wv = w[hd*FF*OO + (k0+kk)*OO + o];
            const float4* pv = reinterpret_cast<const float4*>(&buf[kk*36]);
            #pragma unroll
            for (int q=0;q<8;q++){
                float4 v = pv[q];
                acc[4*q+0]=fmaf(v.x,wv,acc[4*q+0]);
                acc[4*q+1]=fmaf(v.y,wv,acc[4*q+1]);
                acc[4*q+2]=fmaf(v.z,wv,acc[4*q+2]);
                acc[4*q+3]=fmaf(v.w,wv,acc[4*q+3]);
            }
        }
    }
    float av = asrc[tid];   // a_src is (8,32) flat = [hd*32+o] = [tid]
    float dv = adst[tid];
    for (int r=0;r<32;r++){
        int n=b0+r;
        if (n<N){
            hp[((long long)hd*N+n)*OO + o] = acc[r];
            float s = acc[r]*av;
            float d = acc[r]*dv;
            #pragma unroll
            for (int off=16;off;off>>=1){
                s += __shfl_xor_sync(0xffffffffu,s,off);
                d += __shfl_xor_sync(0xffffffffu,d,off);
            }
            if (o==0){ es[hd*N+n]=s; ed[hd*N+n]=d; }
        }
    }
}

// -------- attention: softmax rows + fused attn@hp --------
// one block = (head, 8 node rows); unnormalized exp rows kept in dynamic smem.
template<int SEL>
__global__ void __launch_bounds__(256) k_attn(const int* __restrict__ adj,
        float* __restrict__ attn, const float* __restrict__ bias)
{
    constexpr int N = SEL ? NA : NP;
    const float* hp = SEL ? g_hp2 : g_hp1;
    const float* es = SEL ? g_es2 : g_es1;
    const float* ed = SEL ? g_ed2 : g_ed1;

    extern __shared__ float p[];            // 8*N floats
    __shared__ float red[8];
    __shared__ float sinv[8];
    __shared__ float red2[2048];

    const int hd = blockIdx.y;
    const int n0 = blockIdx.x*8;
    const int tid = threadIdx.x;
    const float* edr = ed + hd*N;

    for (int r=0;r<8;r++){
        int n = n0+r;
        if (n>=N) break;                    // uniform across block
        float esn = es[hd*N+n];
        const int* arow = adj + (long long)n*N;
        float* pr = p + r*N;
        float mx = -3.0e38f;
        for (int m=tid;m<N;m+=256){
            float v = esn + edr[m];
            v = v>0.f ? v : 0.2f*v;         // leaky_relu 0.2
            if (arow[m]==0) v = -1.0e9f;
            pr[m]=v;
            mx = fmaxf(mx,v);
        }
        #pragma unroll
        for (int off=16;off;off>>=1) mx = fmaxf(mx,__shfl_xor_sync(0xffffffffu,mx,off));
        if ((tid&31)==0) red[tid>>5]=mx;
        __syncthreads();
        if (tid==0){
            float v=red[0];
            #pragma unroll
            for (int i=1;i<8;i++) v=fmaxf(v,red[i]);
            red[0]=v;
        }
        __syncthreads();
        float Mx = red[0];
        float sm = 0.f;
        for (int m=tid;m<N;m+=256){
            float q = expf(pr[m]-Mx);
            pr[m]=q;
            sm+=q;
        }
        __syncthreads();
        #pragma unroll
        for (int off=16;off;off>>=1) sm += __shfl_xor_sync(0xffffffffu,sm,off);
        if ((tid&31)==0) red[tid>>5]=sm;
        __syncthreads();
        if (tid==0){
            float v=0.f;
            #pragma unroll
            for (int i=0;i<8;i++) v+=red[i];
            sinv[r]=1.f/v;
        }
        __syncthreads();
        float iv = sinv[r];
        float* ar = attn + ((long long)(hd*N+n))*N;
        for (int m=tid;m<N;m+=256) ar[m] = pr[m]*iv;
        __syncthreads();
    }

    // attn @ hp : GAT1 needs every row; GAT2 only rows n<89 (only h2_word is used)
    if (SEL==0 || n0 < NW){
        const int ml = tid>>5, o = tid&31;
        float acc[8];
        #pragma unroll
        for (int r=0;r<8;r++) acc[r]=0.f;
        const float* hpb = hp + (long long)hd*N*OO + o;
        for (int m=ml;m<N;m+=8){
            float hv = hpb[(long long)m*OO];
            #pragma unroll
            for (int r=0;r<8;r++) acc[r] = fmaf(p[r*N+m], hv, acc[r]);
        }
        #pragma unroll
        for (int r=0;r<8;r++) red2[r*256+tid]=acc[r];
        __syncthreads();
        const int rr = tid>>5;
        const int n = n0+rr;
        float v = 0.f;
        #pragma unroll
        for (int m2=0;m2<8;m2++) v += red2[rr*256 + m2*32 + o];
        if (n < N){
            v = v*sinv[rr] + bias[o];
            if (SEL==0){
                // h1 = elu(transpose->reshape), stored into h1_wp rows 89..
                g_h1wp[(long long)(NW+n)*FF + hd*OO + o] = (v>0.f) ? v : expm1f(v);
            } else if (n < NW){
                g_out2[(hd*NW+n)*OO + o] = v;
            }
        }
    }
}

// -------- mean over heads for h2_word --------
__global__ void k_mean(){
    int i = blockIdx.x*blockDim.x + threadIdx.x;
    if (i < NW*OO){
        float s=0.f;
        #pragma unroll
        for (int h=0;h<HH;h++) s += g_out2[h*NW*OO + i];
        g_h2w[i] = s*0.125f;
    }
}

// -------- x = normalize(concat(uwa[:, :89] @ h2_word, uwa[:, 89:])) --------
__global__ void __launch_bounds__(256) k_x(const float* __restrict__ uwa,
                                           float* __restrict__ xout)
{
    __shared__ float sh2[NW*OO];
    __shared__ float su[UWD];
    __shared__ float redx[256];
    __shared__ float sxv[32];
    __shared__ float ssum;
    const int b = blockIdx.x;
    const int tid = threadIdx.x;

    for (int i=tid;i<NW*OO;i+=256) sh2[i]=g_h2w[i];
    for (int i=tid;i<UWD;i+=256)   su[i]=uwa[(long long)b*UWD+i];
    __syncthreads();

    const int ml=tid>>5, o=tid&31;
    float acc=0.f;
    for (int w=ml;w<NW;w+=8) acc = fmaf(su[w], sh2[w*OO+o], acc);
    redx[tid]=acc;
    __syncthreads();
    if (tid<32){
        float v=0.f;
        #pragma unroll
        for (int m2=0;m2<8;m2++) v += redx[m2*32+tid];
        sxv[tid]=v;
    }
    __syncthreads();
    float xc = (tid<32) ? sxv[tid] : su[NW + tid - 32];
    float s = xc;
    #pragma unroll
    for (int off=16;off;off>>=1) s += __shfl_xor_sync(0xffffffffu,s,off);
    __syncthreads();
    if ((tid&31)==0) redx[tid>>5]=s;
    __syncthreads();
    if (tid==0){
        float v=0.f;
        #pragma unroll
        for (int i=0;i<8;i++) v+=redx[i];
        ssum=v;
    }
    __syncthreads();
    xout[(long long)b*256 + tid] = xc / ssum;
}

// -------- dense head: output1/2, output1_new/2_new, x_temp --------
// 32 rows/block, 128 threads (one column each), col-major shared intermediates.
__global__ void __launch_bounds__(128) k_dense(
    const float* __restrict__ xin, const float* __restrict__ sent,
    const float* __restrict__ Ws1, const float* __restrict__ bs1,
    const float* __restrict__ Ws2, const float* __restrict__ bs2,
    const float* __restrict__ Wf1, const float* __restrict__ bf1,
    const float* __restrict__ Wfa, const float* __restrict__ bfa,
    const float* __restrict__ Wfb, const float* __restrict__ bfb,
    float* __restrict__ o1n, float* __restrict__ o2n, float* __restrict__ xt)
{
    __shared__ float so1[32*128];   // [j][r] col-major
    __shared__ float so2[32*128];
    __shared__ float buf[4096];     // k-tiles (64x36) then relu(t) [j][r]
    const int b0 = blockIdx.x*32;
    const int tid = threadIdx.x;
    float acc[32];

    // output2 = sent @ Ws2 + bs2
    #pragma unroll
    for (int r=0;r<32;r++) acc[r]=0.f;
    for (int k0=0;k0<EE2;k0+=64){
        __syncthreads();
        for (int i=tid;i<2048;i+=128){
            int r=i>>6, kk=i&63;
            buf[kk*36+r] = sent[(long long)(b0+r)*EE2 + (k0+kk)];
        }
        __syncthreads();
        #pragma unroll 2
        for (int kk=0;kk<64;kk++){
            float wv = Ws2[(k0+kk)*128 + tid];
            const float4* pv = reinterpret_cast<const float4*>(&buf[kk*36]);
            #pragma unroll
            for (int q=0;q<8;q++){
                float4 v = pv[q];
                acc[4*q+0]=fmaf(v.x,wv,acc[4*q+0]);
                acc[4*q+1]=fmaf(v.y,wv,acc[4*q+1]);
                acc[4*q+2]=fmaf(v.z,wv,acc[4*q+2]);
                acc[4*q+3]=fmaf(v.w,wv,acc[4*q+3]);
            }
        }
    }
    {
        float bb = bs2[tid];
        #pragma unroll
        for (int r=0;r<32;r++) so2[tid*32+r] = acc[r]+bb;
    }

    // output1 = x @ Ws1 + bs1
    #pragma unroll
    for (int r=0;r<32;r++) acc[r]=0.f;
    for (int k0=0;k0<256;k0+=64){
        __syncthreads();
        for (int i=tid;i<2048;i+=128){
            int r=i>>6, kk=i&63;
            buf[kk*36+r] = xin[(long long)(b0+r)*256 + (k0+kk)];
        }
        __syncthreads();
        #pragma unroll 2
        for (int kk=0;kk<64;kk++){
            float wv = Ws1[(k0+kk)*128 + tid];
            const float4* pv = reinterpret_cast<const float4*>(&buf[kk*36]);
            #pragma unroll
            for (int q=0;q<8;q++){
                float4 v = pv[q];
                acc[4*q+0]=fmaf(v.x,wv,acc[4*q+0]);
                acc[4*q+1]=fmaf(v.y,wv,acc[4*q+1]);
                acc[4*q+2]=fmaf(v.z,wv,acc[4*q+2]);
                acc[4*q+3]=fmaf(v.w,wv,acc[4*q+3]);
            }
        }
    }
    {
        float bb = bs1[tid];
        #pragma unroll
        for (int r=0;r<32;r++) so1[tid*32+r] = acc[r]+bb;
    }
    __syncthreads();

    // o1n = output1 @ Wf1 + bf1 ; o2n = output2 @ Wf1 + bf1
    {
        const int j2 = tid & 63;
        const int half = tid >> 6;
        float a1[16], a2[16];
        #pragma unroll
        for (int q=0;q<16;q++){ a1[q]=0.f; a2[q]=0.f; }
        for (int k=0;k<128;k++){
            float wv = Wf1[k*64+j2];
            const float4* p1 = reinterpret_cast<const float4*>(&so1[k*32 + half*16]);
            const float4* p2 = reinterpret_cast<const float4*>(&so2[k*32 + half*16]);
            #pragma unroll
            for (int q=0;q<4;q++){
                float4 v1=p1[q], v2=p2[q];
                a1[4*q+0]=fmaf(v1.x,wv,a1[4*q+0]); a2[4*q+0]=fmaf(v2.x,wv,a2[4*q+0]);
                a1[4*q+1]=fmaf(v1.y,wv,a1[4*q+1]); a2[4*q+1]=fmaf(v2.y,wv,a2[4*q+1]);
                a1[4*q+2]=fmaf(v1.z,wv,a1[4*q+2]); a2[4*q+2]=fmaf(v2.z,wv,a2[4*q+2]);
                a1[4*q+3]=fmaf(v1.w,wv,a1[4*q+3]); a2[4*q+3]=fmaf(v2.w,wv,a2[4*q+3]);
            }
        }
        float bb = bf1[j2];
        #pragma unroll
        for (int q=0;q<16;q++){
            int r = half*16+q;
            o1n[(long long)(b0+r)*64 + j2] = a1[q]+bb;
            o2n[(long long)(b0+r)*64 + j2] = a2[q]+bb;
        }
    }

    // t = relu(concat(output1,output2) @ Wfa + bfa)
    #pragma unroll
    for (int r=0;r<32;r++) acc[r]=0.f;
    for (int k=0;k<128;k++){
        float wv = Wfa[k*128+tid];
        const float4* pv = reinterpret_cast<const float4*>(&so1[k*32]);
        #pragma unroll
        for (int q=0;q<8;q++){
            float4 v = pv[q];
            acc[4*q+0]=fmaf(v.x,wv,acc[4*q+0]);
            acc[4*q+1]=fmaf(v.y,wv,acc[4*q+1]);
            acc[4*q+2]=fmaf(v.z,wv,acc[4*q+2]);
            acc[4*q+3]=fmaf(v.w,wv,acc[4*q+3]);
        }
    }
    for (int k=0;k<128;k++){
        float wv = Wfa[(128+k)*128+tid];
        const float4* pv = reinterpret_cast<const float4*>(&so2[k*32]);
        #pragma unroll
        for (int q=0;q<8;q++){
            float4 v = pv[q];
            acc[4*q+0]=fmaf(v.x,wv,acc[4*q+0]);
            acc[4*q+1]=fmaf(v.y,wv,acc[4*q+1]);
            acc[4*q+2]=fmaf(v.z,wv,acc[4*q+2]);
            acc[4*q+3]=fmaf(v.w,wv,acc[4*q+3]);
        }
    }
    __syncthreads();
    {
        float bb = bfa[tid];
        float4* stp = reinterpret_cast<float4*>(&buf[tid*32]);
        #pragma unroll
        for (int q=0;q<8;q++){
            float4 v;
            v.x = fmaxf(acc[4*q+0]+bb, 0.f);
            v.y = fmaxf(acc[4*q+1]+bb, 0.f);
            v.z = fmaxf(acc[4*q+2]+bb, 0.f);
            v.w = fmaxf(acc[4*q+3]+bb, 0.f);
            stp[q]=v;
        }
    }
    __syncthreads();
    // x_temp = t @ Wfb + bfb
    for (int i=tid;i<160;i+=128){
        int r=i/5, c=i%5;
        float s = bfb[c];
        for (int j=0;j<128;j++) s = fmaf(buf[j*32+r], Wfb[j*5+c], s);
        xt[(long long)(b0+r)*5 + c] = s;
    }
}

extern "C" void kernel_launch(void* const* d_in, const int* in_sizes, int n_in,
                              void* d_out, int out_size)
{
    (void)in_sizes; (void)n_in; (void)out_size;
    const float* pern  = (const float*)d_in[0];
    const float* wordf = (const float*)d_in[1];
    const int*   padj  = (const int*)d_in[2];
    const int*   wpadj = (const int*)d_in[3];
    const float* uwa   = (const float*)d_in[4];
    const float* sent  = (const float*)d_in[5];
    const float* w1    = (const float*)d_in[6];
    const float* as1   = (const float*)d_in[7];
    const float* ad1   = (const float*)d_in[8];
    const float* b1    = (const float*)d_in[9];
    const float* w2    = (const float*)d_in[10];
    const float* as2   = (const float*)d_in[11];
    const float* ad2   = (const float*)d_in[12];
    const float* b2    = (const float*)d_in[13];
    const float* Ws1   = (const float*)d_in[14];
    const float* bs1   = (const float*)d_in[15];
    const float* Ws2   = (const float*)d_in[16];
    const float* bs2   = (const float*)d_in[17];
    const float* Wf1   = (const float*)d_in[18];
    const float* bf1   = (const float*)d_in[19];
    const float* Wfa   = (const float*)d_in[20];
    const float* bfa   = (const float*)d_in[21];
    const float* Wfb   = (const float*)d_in[22];
    const float* bfb   = (const float*)d_in[23];
    float* out = (float*)d_out;

    cudaFuncSetAttribute(k_attn<0>, cudaFuncAttributeMaxDynamicSharedMemorySize, 8*NP*4);
    cudaFuncSetAttribute(k_attn<1>, cudaFuncAttributeMaxDynamicSharedMemorySize, 8*NA*4);

    k_copy_word<<<(NW*FF+255)/256, 256>>>(wordf);
    k_hp<0><<<(NP+31)/32, 256>>>(pern, w1, as1, ad1);
    k_attn<0><<<dim3(NP/8, HH), 256, 8*NP*4>>>(padj, out+OFF_APP, b1);
    k_hp<1><<<(NA+31)/32, 256>>>(pern, w2, as2, ad2);
    k_attn<1><<<dim3((NA+7)/8, HH), 256, 8*NA*4>>>(wpadj, out+OFF_AWP, b2);
    k_mean<<<(NW*OO+255)/256, 256>>>();
    k_x<<<BB, 256>>>(uwa, out+OFF_X);
    k_dense<<<BB/32, 128>>>(out+OFF_X, sent, Ws1,bs1,Ws2,bs2,Wf1,bf1,Wfa,bfa,Wfb,bfb,
                            out+OFF_O1N, out+OFF_O2N, out+OFF_XT);
}

// round 3
// speedup vs baseline: 1.3799x; 1.3799x over previous
#include <cuda_runtime.h>
#include <math.h>

#define NP 2048
#define NW 89
#define NA 2137
#define BB 16384
#define EE2 768
#define UWD 313
#define HH 8
#define FF 256
#define OO 32

// output layout: concat of flattened outputs in reference return order
#define OFF_O1N 0LL                 // (B,64)
#define OFF_O2N 1048576LL           // (B,64)
#define OFF_XT  2097152LL           // (B,5)
#define OFF_APP 2179072LL           // (8,2048,2048)
#define OFF_AWP 35733504LL          // (8,2137,2137)
#define OFF_X   72267656LL          // (B,256)

// -------- scratch (no allocations allowed -> device globals) --------
__device__ float g_hp1[HH*NP*OO];
__device__ float g_es1[HH*NP];
__device__ float g_ed1[HH*NP];
__device__ float g_h1wp[NA*FF];
__device__ float g_hp2[HH*NA*OO];
__device__ float g_es2[HH*NA];
__device__ float g_ed2[HH*NA];
__device__ float g_out2[HH*NW*OO];
__device__ float g_h2w[NW*OO];

// -------- copy word features into top of h1_wp --------
__global__ void k_copy_word(const float* __restrict__ wf){
    int i = blockIdx.x*blockDim.x + threadIdx.x;
    if (i < NW*FF) g_h1wp[i] = wf[i];
}

// -------- hp = einsum('nf,hfo->hno'), plus e_src/e_dst --------
// one block = (32 rows, 1 head). 256 threads = 32 cols x 8 row-groups, 4 rows/thread.
template<int SEL>
__global__ void __launch_bounds__(256) k_hp(const float* __restrict__ hin,
        const float* __restrict__ w, const float* __restrict__ asrc,
        const float* __restrict__ adst)
{
    constexpr int N = SEL ? NA : NP;
    const float* h  = SEL ? g_h1wp : hin;
    float* hp = SEL ? g_hp2 : g_hp1;
    float* es = SEL ? g_es2 : g_es1;
    float* ed = SEL ? g_ed2 : g_ed1;

    extern __shared__ float sm[];
    float* sw = sm;          // [256][32] this head's weight slice
    float* sh = sm + 8192;   // [32][256] row tile

    const int hd = blockIdx.y;
    const int b0 = blockIdx.x*32;
    const int tid = threadIdx.x;

    {
        const float4* src = reinterpret_cast<const float4*>(w + hd*FF*OO);
        float4* dst = reinterpret_cast<float4*>(sw);
        #pragma unroll
        for (int i=0;i<8;i++) dst[tid + i*256] = src[tid + i*256];
    }
    for (int i=tid;i<2048;i+=256){
        int r=i>>6, c4=i&63;
        int n=b0+r;
        float4 v = make_float4(0.f,0.f,0.f,0.f);
        if (n<N) v = *reinterpret_cast<const float4*>(h + (long long)n*FF + c4*4);
        *reinterpret_cast<float4*>(&sh[r*256 + c4*4]) = v;
    }
    __syncthreads();

    const int o = tid&31, rg = tid>>5;
    float acc[4] = {0.f,0.f,0.f,0.f};
    const float* shr = sh + rg*4*256;
    #pragma unroll 2
    for (int k0=0;k0<256;k0+=4){
        float w0=sw[(k0+0)*32+o], w1=sw[(k0+1)*32+o];
        float w2=sw[(k0+2)*32+o], w3=sw[(k0+3)*32+o];
        #pragma unroll
        for (int q=0;q<4;q++){
            float4 hv = *reinterpret_cast<const float4*>(&shr[q*256+k0]);
            acc[q]=fmaf(hv.x,w0,acc[q]);
            acc[q]=fmaf(hv.y,w1,acc[q]);
            acc[q]=fmaf(hv.z,w2,acc[q]);
            acc[q]=fmaf(hv.w,w3,acc[q]);
        }
    }
    float av = asrc[hd*32+o];
    float dv = adst[hd*32+o];
    #pragma unroll
    for (int q=0;q<4;q++){
        int n=b0+rg*4+q;
        if (n<N) hp[((long long)hd*N+n)*OO+o]=acc[q];
        float s=acc[q]*av, d=acc[q]*dv;
        #pragma unroll
        for (int off=16;off;off>>=1){
            s+=__shfl_xor_sync(0xffffffffu,s,off);
            d+=__shfl_xor_sync(0xffffffffu,d,off);
        }
        if (o==0 && n<N){ es[hd*N+n]=s; ed[hd*N+n]=d; }
    }
}

// -------- attention: softmax rows + fused attn@hp --------
// grid = (heads, rowgroups): the 8 heads of one rowgroup are ADJACENT block ids
// so the adjacency rows are fetched from DRAM once and hit L2 for the other 7.
template<int SEL>
__global__ void __launch_bounds__(256) k_attn(const int* __restrict__ adj,
        float* __restrict__ attn, const float* __restrict__ bias)
{
    constexpr int N = SEL ? NA : NP;
    const float* hp = SEL ? g_hp2 : g_hp1;
    const float* es = SEL ? g_es2 : g_es1;
    const float* ed = SEL ? g_ed2 : g_ed1;

    extern __shared__ float p[];            // 8*N floats
    __shared__ float red[8];
    __shared__ float sinv[8];
    __shared__ float red2[2048];

    const int hd = blockIdx.x;
    const int n0 = blockIdx.y*8;
    const int tid = threadIdx.x;
    const float* edr = ed + hd*N;

    for (int r=0;r<8;r++){
        int n = n0+r;
        if (n>=N) break;                    // uniform across block
        float esn = es[hd*N+n];
        const int* arow = adj + (long long)n*N;
        float* pr = p + r*N;
        float mx = -3.0e38f;
        for (int m=tid;m<N;m+=256){
            float v = esn + edr[m];
            v = v>0.f ? v : 0.2f*v;         // leaky_relu 0.2
            if (arow[m]==0) v = -1.0e9f;
            pr[m]=v;
            mx = fmaxf(mx,v);
        }
        #pragma unroll
        for (int off=16;off;off>>=1) mx = fmaxf(mx,__shfl_xor_sync(0xffffffffu,mx,off));
        if ((tid&31)==0) red[tid>>5]=mx;
        __syncthreads();
        if (tid==0){
            float v=red[0];
            #pragma unroll
            for (int i=1;i<8;i++) v=fmaxf(v,red[i]);
            red[0]=v;
        }
        __syncthreads();
        float Mx = red[0];
        float sm = 0.f;
        for (int m=tid;m<N;m+=256){
            float q = __expf(pr[m]-Mx);
            pr[m]=q;
            sm+=q;
        }
        __syncthreads();
        #pragma unroll
        for (int off=16;off;off>>=1) sm += __shfl_xor_sync(0xffffffffu,sm,off);
        if ((tid&31)==0) red[tid>>5]=sm;
        __syncthreads();
        if (tid==0){
            float v=0.f;
            #pragma unroll
            for (int i=0;i<8;i++) v+=red[i];
            sinv[r]=1.f/v;
        }
        __syncthreads();
        float iv = sinv[r];
        float* ar = attn + ((long long)(hd*N+n))*N;
        for (int m=tid;m<N;m+=256) ar[m] = pr[m]*iv;
        __syncthreads();
    }

    // attn @ hp : GAT1 needs every row; GAT2 only rows n<89 (only h2_word is used)
    if (SEL==0 || n0 < NW){
        const int ml = tid>>5, o = tid&31;
        float acc[8];
        #pragma unroll
        for (int r=0;r<8;r++) acc[r]=0.f;
        const float* hpb = hp + (long long)hd*N*OO + o;
        for (int m=ml;m<N;m+=8){
            float hv = hpb[(long long)m*OO];
            #pragma unroll
            for (int r=0;r<8;r++) acc[r] = fmaf(p[r*N+m], hv, acc[r]);
        }
        #pragma unroll
        for (int r=0;r<8;r++) red2[r*256+tid]=acc[r];
        __syncthreads();
        const int rr = tid>>5;
        const int n = n0+rr;
        float v = 0.f;
        #pragma unroll
        for (int m2=0;m2<8;m2++) v += red2[rr*256 + m2*32 + o];
        if (n < N){
            v = v*sinv[rr] + bias[o];
            if (SEL==0){
                g_h1wp[(long long)(NW+n)*FF + hd*OO + o] = (v>0.f) ? v : expm1f(v);
            } else if (n < NW){
                g_out2[(hd*NW+n)*OO + o] = v;
            }
        }
    }
}

// -------- mean over heads for h2_word --------
__global__ void k_mean(){
    int i = blockIdx.x*blockDim.x + threadIdx.x;
    if (i < NW*OO){
        float s=0.f;
        #pragma unroll
        for (int h=0;h<HH;h++) s += g_out2[h*NW*OO + i];
        g_h2w[i] = s*0.125f;
    }
}

// -------- x = normalize(concat(uwa[:, :89] @ h2_word, uwa[:, 89:])) --------
// 32 rows per block (512 blocks): h2w loaded once per block instead of per row.
__global__ void __launch_bounds__(256) k_x2(const float* __restrict__ uwa,
                                            float* __restrict__ xout)
{
    extern __shared__ float sm[];
    float* su   = sm;              // [32][320]
    float* sh2  = sm + 32*320;     // [89][32]
    float* sxm  = sh2 + NW*OO;     // [32][32]
    float* srow = sxm + 1024;      // [32] reciprocal row sums

    const int b0 = blockIdx.x*32;
    const int tid = threadIdx.x;

    for (int i=tid;i<NW*OO;i+=256) sh2[i]=g_h2w[i];
    for (int i=tid;i<32*UWD;i+=256){
        int r=i/UWD, w=i-r*UWD;
        su[r*320+w]=uwa[(long long)(b0+r)*UWD + w];
    }
    __syncthreads();

    const int o = tid&31, rg = tid>>5;
    float acc[4]={0.f,0.f,0.f,0.f};
    for (int w=0;w<NW;w++){
        float hv = sh2[w*32+o];
        #pragma unroll
        for (int q=0;q<4;q++) acc[q]=fmaf(su[(rg*4+q)*320+w], hv, acc[q]);
    }
    float ts[4]={0.f,0.f,0.f,0.f};
    for (int w=NW+o; w<UWD; w+=32){
        #pragma unroll
        for (int q=0;q<4;q++) ts[q]+=su[(rg*4+q)*320+w];
    }
    #pragma unroll
    for (int q=0;q<4;q++){
        sxm[(rg*4+q)*32+o]=acc[q];
        float s = acc[q]+ts[q];
        #pragma unroll
        for (int off=16;off;off>>=1) s += __shfl_xor_sync(0xffffffffu,s,off);
        if (o==0) srow[rg*4+q]=1.f/s;
    }
    __syncthreads();
    for (int i=tid;i<32*256;i+=256){
        int r=i>>8, c=i&255;
        float v = (c<32) ? sxm[r*32+c] : su[r*320 + 57 + c];
        xout[(long long)(b0+r)*256 + c] = v*srow[r];
    }
}

// -------- dense head: output1/2, output1_new/2_new, x_temp --------
__global__ void __launch_bounds__(128) k_dense(
    const float* __restrict__ xin, const float* __restrict__ sent,
    const float* __restrict__ Ws1, const float* __restrict__ bs1,
    const float* __restrict__ Ws2, const float* __restrict__ bs2,
    const float* __restrict__ Wf1, const float* __restrict__ bf1,
    const float* __restrict__ Wfa, const float* __restrict__ bfa,
    const float* __restrict__ Wfb, const float* __restrict__ bfb,
    float* __restrict__ o1n, float* __restrict__ o2n, float* __restrict__ xt)
{
    __shared__ float so1[32*128];   // [j][r] col-major
    __shared__ float so2[32*128];
    __shared__ float buf[4096];     // k-tiles (64x36) then relu(t) [j][r]
    const int b0 = blockIdx.x*32;
    const int tid = threadIdx.x;
    float acc[32];

    // output2 = sent @ Ws2 + bs2
    #pragma unroll
    for (int r=0;r<32;r++) acc[r]=0.f;
    for (int k0=0;k0<EE2;k0+=64){
        __syncthreads();
        for (int i=tid;i<2048;i+=128){
            int r=i>>6, kk=i&63;
            buf[kk*36+r] = sent[(long long)(b0+r)*EE2 + (k0+kk)];
        }
        __syncthreads();
        #pragma unroll 2
        for (int kk=0;kk<64;kk++){
            float wv = Ws2[(k0+kk)*128 + tid];
            const float4* pv = reinterpret_cast<const float4*>(&buf[kk*36]);
            #pragma unroll
            for (int q=0;q<8;q++){
                float4 v = pv[q];
                acc[4*q+0]=fmaf(v.x,wv,acc[4*q+0]);
                acc[4*q+1]=fmaf(v.y,wv,acc[4*q+1]);
                acc[4*q+2]=fmaf(v.z,wv,acc[4*q+2]);
                acc[4*q+3]=fmaf(v.w,wv,acc[4*q+3]);
            }
        }
    }
    {
        float bb = bs2[tid];
        #pragma unroll
        for (int r=0;r<32;r++) so2[tid*32+r] = acc[r]+bb;
    }

    // output1 = x @ Ws1 + bs1
    #pragma unroll
    for (int r=0;r<32;r++) acc[r]=0.f;
    for (int k0=0;k0<256;k0+=64){
        __syncthreads();
        for (int i=tid;i<2048;i+=128){
            int r=i>>6, kk=i&63;
            buf[kk*36+r] = xin[(long long)(b0+r)*256 + (k0+kk)];
        }
        __syncthreads();
        #pragma unroll 2
        for (int kk=0;kk<64;kk++){
            float wv = Ws1[(k0+kk)*128 + tid];
            const float4* pv = reinterpret_cast<const float4*>(&buf[kk*36]);
            #pragma unroll
            for (int q=0;q<8;q++){
                float4 v = pv[q];
                acc[4*q+0]=fmaf(v.x,wv,acc[4*q+0]);
                acc[4*q+1]=fmaf(v.y,wv,acc[4*q+1]);
                acc[4*q+2]=fmaf(v.z,wv,acc[4*q+2]);
                acc[4*q+3]=fmaf(v.w,wv,acc[4*q+3]);
            }
        }
    }
    {
        float bb = bs1[tid];
        #pragma unroll
        for (int r=0;r<32;r++) so1[tid*32+r] = acc[r]+bb;
    }
    __syncthreads();

    // o1n = output1 @ Wf1 + bf1 ; o2n = output2 @ Wf1 + bf1
    {
        const int j2 = tid & 63;
        const int half = tid >> 6;
        float a1[16], a2[16];
        #pragma unroll
        for (int q=0;q<16;q++){ a1[q]=0.f; a2[q]=0.f; }
        for (int k=0;k<128;k++){
            float wv = Wf1[k*64+j2];
            const float4* p1 = reinterpret_cast<const float4*>(&so1[k*32 + half*16]);
            const float4* p2 = reinterpret_cast<const float4*>(&so2[k*32 + half*16]);
            #pragma unroll
            for (int q=0;q<4;q++){
                float4 v1=p1[q], v2=p2[q];
                a1[4*q+0]=fmaf(v1.x,wv,a1[4*q+0]); a2[4*q+0]=fmaf(v2.x,wv,a2[4*q+0]);
                a1[4*q+1]=fmaf(v1.y,wv,a1[4*q+1]); a2[4*q+1]=fmaf(v2.y,wv,a2[4*q+1]);
                a1[4*q+2]=fmaf(v1.z,wv,a1[4*q+2]); a2[4*q+2]=fmaf(v2.z,wv,a2[4*q+2]);
                a1[4*q+3]=fmaf(v1.w,wv,a1[4*q+3]); a2[4*q+3]=fmaf(v2.w,wv,a2[4*q+3]);
            }
        }
        float bb = bf1[j2];
        #pragma unroll
        for (int q=0;q<16;q++){
            int r = half*16+q;
            o1n[(long long)(b0+r)*64 + j2] = a1[q]+bb;
            o2n[(long long)(b0+r)*64 + j2] = a2[q]+bb;
        }
    }

    // t = relu(concat(output1,output2) @ Wfa + bfa)
    #pragma unroll
    for (int r=0;r<32;r++) acc[r]=0.f;
    for (int k=0;k<128;k++){
        float wv = Wfa[k*128+tid];
        const float4* pv = reinterpret_cast<const float4*>(&so1[k*32]);
        #pragma unroll
        for (int q=0;q<8;q++){
            float4 v = pv[q];
            acc[4*q+0]=fmaf(v.x,wv,acc[4*q+0]);
            acc[4*q+1]=fmaf(v.y,wv,acc[4*q+1]);
            acc[4*q+2]=fmaf(v.z,wv,acc[4*q+2]);
            acc[4*q+3]=fmaf(v.w,wv,acc[4*q+3]);
        }
    }
    for (int k=0;k<128;k++){
        float wv = Wfa[(128+k)*128+tid];
        const float4* pv = reinterpret_cast<const float4*>(&so2[k*32]);
        #pragma unroll
        for (int q=0;q<8;q++){
            float4 v = pv[q];
            acc[4*q+0]=fmaf(v.x,wv,acc[4*q+0]);
            acc[4*q+1]=fmaf(v.y,wv,acc[4*q+1]);
            acc[4*q+2]=fmaf(v.z,wv,acc[4*q+2]);
            acc[4*q+3]=fmaf(v.w,wv,acc[4*q+3]);
        }
    }
    __syncthreads();
    {
        float bb = bfa[tid];
        float4* stp = reinterpret_cast<float4*>(&buf[tid*32]);
        #pragma unroll
        for (int q=0;q<8;q++){
            float4 v;
            v.x = fmaxf(acc[4*q+0]+bb, 0.f);
            v.y = fmaxf(acc[4*q+1]+bb, 0.f);
            v.z = fmaxf(acc[4*q+2]+bb, 0.f);
            v.w = fmaxf(acc[4*q+3]+bb, 0.f);
            stp[q]=v;
        }
    }
    __syncthreads();
    // x_temp = t @ Wfb + bfb
    for (int i=tid;i<160;i+=128){
        int r=i/5, c=i%5;
        float s = bfb[c];
        for (int j=0;j<128;j++) s = fmaf(buf[j*32+r], Wfb[j*5+c], s);
        xt[(long long)(b0+r)*5 + c] = s;
    }
}

extern "C" void kernel_launch(void* const* d_in, const int* in_sizes, int n_in,
                              void* d_out, int out_size)
{
    (void)in_sizes; (void)n_in; (void)out_size;
    const float* pern  = (const float*)d_in[0];
    const float* wordf = (const float*)d_in[1];
    const int*   padj  = (const int*)d_in[2];
    const int*   wpadj = (const int*)d_in[3];
    const float* uwa   = (const float*)d_in[4];
    const float* sent  = (const float*)d_in[5];
    const float* w1    = (const float*)d_in[6];
    const float* as1   = (const float*)d_in[7];
    const float* ad1   = (const float*)d_in[8];
    const float* b1    = (const float*)d_in[9];
    const float* w2    = (const float*)d_in[10];
    const float* as2   = (const float*)d_in[11];
    const float* ad2   = (const float*)d_in[12];
    const float* b2    = (const float*)d_in[13];
    const float* Ws1   = (const float*)d_in[14];
    const float* bs1   = (const float*)d_in[15];
    const float* Ws2   = (const float*)d_in[16];
    const float* bs2   = (const float*)d_in[17];
    const float* Wf1   = (const float*)d_in[18];
    const float* bf1   = (const float*)d_in[19];
    const float* Wfa   = (const float*)d_in[20];
    const float* bfa   = (const float*)d_in[21];
    const float* Wfb   = (const float*)d_in[22];
    const float* bfb   = (const float*)d_in[23];
    float* out = (float*)d_out;

    cudaFuncSetAttribute(k_hp<0>,  cudaFuncAttributeMaxDynamicSharedMemorySize, 65536);
    cudaFuncSetAttribute(k_hp<1>,  cudaFuncAttributeMaxDynamicSharedMemorySize, 65536);
    cudaFuncSetAttribute(k_attn<0>,cudaFuncAttributeMaxDynamicSharedMemorySize, 8*NP*4);
    cudaFuncSetAttribute(k_attn<1>,cudaFuncAttributeMaxDynamicSharedMemorySize, 8*NA*4);
    cudaFuncSetAttribute(k_x2,     cudaFuncAttributeMaxDynamicSharedMemorySize, 60000);

    k_copy_word<<<(NW*FF+255)/256, 256>>>(wordf);
    k_hp<0><<<dim3(NP/32, HH), 256, 65536>>>(pern, w1, as1, ad1);
    k_attn<0><<<dim3(HH, NP/8), 256, 8*NP*4>>>(padj, out+OFF_APP, b1);
    k_hp<1><<<dim3((NA+31)/32, HH), 256, 65536>>>(pern, w2, as2, ad2);
    k_attn<1><<<dim3(HH, (NA+7)/8), 256, 8*NA*4>>>(wpadj, out+OFF_AWP, b2);
    k_mean<<<(NW*OO+255)/256, 256>>>();
    k_x2<<<BB/32, 256, (32*320 + NW*OO + 1024 + 32)*4>>>(uwa, out+OFF_X);
    k_dense<<<BB/32, 128>>>(out+OFF_X, sent, Ws1,bs1,Ws2,bs2,Wf1,bf1,Wfa,bfa,Wfb,bfb,
                            out+OFF_O1N, out+OFF_O2N, out+OFF_XT);
}

// round 4
// speedup vs baseline: 1.3804x; 1.0004x over previous
#include <cuda_runtime.h>
#include <math.h>

#define NP 2048
#define NW 89
#define NA 2137
#define BB 16384
#define EE2 768
#define UWD 313
#define HH 8
#define FF 256
#define OO 32

// output layout: concat of flattened outputs in reference return order
#define OFF_O1N 0LL                 // (B,64)
#define OFF_O2N 1048576LL           // (B,64)
#define OFF_XT  2097152LL           // (B,5)
#define OFF_APP 2179072LL           // (8,2048,2048)
#define OFF_AWP 35733504LL          // (8,2137,2137)
#define OFF_X   72267656LL          // (B,256)

// -------- scratch (no allocations allowed -> device globals) --------
__device__ float g_hp1[HH*NP*OO];
__device__ float g_es1[HH*NP];
__device__ float g_ed1[HH*NP];
__device__ float g_h1wp[NA*FF];
__device__ float g_hp2[HH*NA*OO];
__device__ float g_es2[HH*NA];
__device__ float g_ed2[HH*NA];
__device__ float g_out2[HH*NW*OO];
__device__ float g_h2w[NW*OO];

// -------- copy word features into top of h1_wp --------
__global__ void k_copy_word(const float* __restrict__ wf){
    int i = blockIdx.x*blockDim.x + threadIdx.x;
    if (i < NW*FF) g_h1wp[i] = wf[i];
}

// -------- hp = einsum('nf,hfo->hno'), plus e_src/e_dst --------
// one block = (32 rows, 1 head). 256 threads = 32 cols x 8 row-groups, 4 rows/thread.
template<int SEL>
__global__ void __launch_bounds__(256) k_hp(const float* __restrict__ hin,
        const float* __restrict__ w, const float* __restrict__ asrc,
        const float* __restrict__ adst)
{
    constexpr int N = SEL ? NA : NP;
    const float* h  = SEL ? g_h1wp : hin;
    float* hp = SEL ? g_hp2 : g_hp1;
    float* es = SEL ? g_es2 : g_es1;
    float* ed = SEL ? g_ed2 : g_ed1;

    extern __shared__ float sm[];
    float* sw = sm;          // [256][32] this head's weight slice
    float* sh = sm + 8192;   // [32][256] row tile

    const int hd = blockIdx.y;
    const int b0 = blockIdx.x*32;
    const int tid = threadIdx.x;

    {
        const float4* src = reinterpret_cast<const float4*>(w + hd*FF*OO);
        float4* dst = reinterpret_cast<float4*>(sw);
        #pragma unroll
        for (int i=0;i<8;i++) dst[tid + i*256] = src[tid + i*256];
    }
    for (int i=tid;i<2048;i+=256){
        int r=i>>6, c4=i&63;
        int n=b0+r;
        float4 v = make_float4(0.f,0.f,0.f,0.f);
        if (n<N) v = *reinterpret_cast<const float4*>(h + (long long)n*FF + c4*4);
        *reinterpret_cast<float4*>(&sh[r*256 + c4*4]) = v;
    }
    __syncthreads();

    const int o = tid&31, rg = tid>>5;
    float acc[4] = {0.f,0.f,0.f,0.f};
    const float* shr = sh + rg*4*256;
    #pragma unroll 2
    for (int k0=0;k0<256;k0+=4){
        float w0=sw[(k0+0)*32+o], w1=sw[(k0+1)*32+o];
        float w2=sw[(k0+2)*32+o], w3=sw[(k0+3)*32+o];
        #pragma unroll
        for (int q=0;q<4;q++){
            float4 hv = *reinterpret_cast<const float4*>(&shr[q*256+k0]);
            acc[q]=fmaf(hv.x,w0,acc[q]);
            acc[q]=fmaf(hv.y,w1,acc[q]);
            acc[q]=fmaf(hv.z,w2,acc[q]);
            acc[q]=fmaf(hv.w,w3,acc[q]);
        }
    }
    float av = asrc[hd*32+o];
    float dv = adst[hd*32+o];
    #pragma unroll
    for (int q=0;q<4;q++){
        int n=b0+rg*4+q;
        if (n<N) hp[((long long)hd*N+n)*OO+o]=acc[q];
        float s=acc[q]*av, d=acc[q]*dv;
        #pragma unroll
        for (int off=16;off;off>>=1){
            s+=__shfl_xor_sync(0xffffffffu,s,off);
            d+=__shfl_xor_sync(0xffffffffu,d,off);
        }
        if (o==0 && n<N){ es[hd*N+n]=s; ed[hd*N+n]=d; }
    }
}

// -------- attention: softmax rows + fused attn@hp --------
// grid = (heads, rowgroups): the 8 heads of one rowgroup are ADJACENT block ids
// so the adjacency rows are fetched from DRAM once and hit L2 for the other 7.
template<int SEL>
__global__ void __launch_bounds__(256) k_attn(const int* __restrict__ adj,
        float* __restrict__ attn, const float* __restrict__ bias)
{
    constexpr int N = SEL ? NA : NP;
    const float* hp = SEL ? g_hp2 : g_hp1;
    const float* es = SEL ? g_es2 : g_es1;
    const float* ed = SEL ? g_ed2 : g_ed1;

    extern __shared__ float p[];            // 8*N floats
    __shared__ float red[8];
    __shared__ float sinv[8];
    __shared__ float red2[2048];

    const int hd = blockIdx.x;
    const int n0 = blockIdx.y*8;
    const int tid = threadIdx.x;
    const float* edr = ed + hd*N;

    for (int r=0;r<8;r++){
        int n = n0+r;
        if (n>=N) break;                    // uniform across block
        float esn = es[hd*N+n];
        const int* arow = adj + (long long)n*N;
        float* pr = p + r*N;
        float mx = -3.0e38f;
        for (int m=tid;m<N;m+=256){
            float v = esn + edr[m];
            v = v>0.f ? v : 0.2f*v;         // leaky_relu 0.2
            if (arow[m]==0) v = -1.0e9f;
            pr[m]=v;
            mx = fmaxf(mx,v);
        }
        #pragma unroll
        for (int off=16;off;off>>=1) mx = fmaxf(mx,__shfl_xor_sync(0xffffffffu,mx,off));
        if ((tid&31)==0) red[tid>>5]=mx;
        __syncthreads();
        if (tid==0){
            float v=red[0];
            #pragma unroll
            for (int i=1;i<8;i++) v=fmaxf(v,red[i]);
            red[0]=v;
        }
        __syncthreads();
        float Mx = red[0];
        float sm = 0.f;
        for (int m=tid;m<N;m+=256){
            float q = __expf(pr[m]-Mx);
            pr[m]=q;
            sm+=q;
        }
        __syncthreads();
        #pragma unroll
        for (int off=16;off;off>>=1) sm += __shfl_xor_sync(0xffffffffu,sm,off);
        if ((tid&31)==0) red[tid>>5]=sm;
        __syncthreads();
        if (tid==0){
            float v=0.f;
            #pragma unroll
            for (int i=0;i<8;i++) v+=red[i];
            sinv[r]=1.f/v;
        }
        __syncthreads();
        float iv = sinv[r];
        float* ar = attn + ((long long)(hd*N+n))*N;
        for (int m=tid;m<N;m+=256) ar[m] = pr[m]*iv;
        __syncthreads();
    }

    // attn @ hp : GAT1 needs every row; GAT2 only rows n<89 (only h2_word is used)
    if (SEL==0 || n0 < NW){
        const int ml = tid>>5, o = tid&31;
        float acc[8];
        #pragma unroll
        for (int r=0;r<8;r++) acc[r]=0.f;
        const float* hpb = hp + (long long)hd*N*OO + o;
        for (int m=ml;m<N;m+=8){
            float hv = hpb[(long long)m*OO];
            #pragma unroll
            for (int r=0;r<8;r++) acc[r] = fmaf(p[r*N+m], hv, acc[r]);
        }
        #pragma unroll
        for (int r=0;r<8;r++) red2[r*256+tid]=acc[r];
        __syncthreads();
        const int rr = tid>>5;
        const int n = n0+rr;
        float v = 0.f;
        #pragma unroll
        for (int m2=0;m2<8;m2++) v += red2[rr*256 + m2*32 + o];
        if (n < N){
            v = v*sinv[rr] + bias[o];
            if (SEL==0){
                g_h1wp[(long long)(NW+n)*FF + hd*OO + o] = (v>0.f) ? v : expm1f(v);
            } else if (n < NW){
                g_out2[(hd*NW+n)*OO + o] = v;
            }
        }
    }
}

// -------- mean over heads for h2_word --------
__global__ void k_mean(){
    int i = blockIdx.x*blockDim.x + threadIdx.x;
    if (i < NW*OO){
        float s=0.f;
        #pragma unroll
        for (int h=0;h<HH;h++) s += g_out2[h*NW*OO + i];
        g_h2w[i] = s*0.125f;
    }
}

// -------- x = normalize(concat(uwa[:, :89] @ h2_word, uwa[:, 89:])) --------
// 32 rows per block (512 blocks): h2w loaded once per block instead of per row.
__global__ void __launch_bounds__(256) k_x2(const float* __restrict__ uwa,
                                            float* __restrict__ xout)
{
    extern __shared__ float sm[];
    float* su   = sm;              // [32][320]
    float* sh2  = sm + 32*320;     // [89][32]
    float* sxm  = sh2 + NW*OO;     // [32][32]
    float* srow = sxm + 1024;      // [32] reciprocal row sums

    const int b0 = blockIdx.x*32;
    const int tid = threadIdx.x;

    for (int i=tid;i<NW*OO;i+=256) sh2[i]=g_h2w[i];
    for (int i=tid;i<32*UWD;i+=256){
        int r=i/UWD, w=i-r*UWD;
        su[r*320+w]=uwa[(long long)(b0+r)*UWD + w];
    }
    __syncthreads();

    const int o = tid&31, rg = tid>>5;
    float acc[4]={0.f,0.f,0.f,0.f};
    for (int w=0;w<NW;w++){
        float hv = sh2[w*32+o];
        #pragma unroll
        for (int q=0;q<4;q++) acc[q]=fmaf(su[(rg*4+q)*320+w], hv, acc[q]);
    }
    float ts[4]={0.f,0.f,0.f,0.f};
    for (int w=NW+o; w<UWD; w+=32){
        #pragma unroll
        for (int q=0;q<4;q++) ts[q]+=su[(rg*4+q)*320+w];
    }
    #pragma unroll
    for (int q=0;q<4;q++){
        sxm[(rg*4+q)*32+o]=acc[q];
        float s = acc[q]+ts[q];
        #pragma unroll
        for (int off=16;off;off>>=1) s += __shfl_xor_sync(0xffffffffu,s,off);
        if (o==0) srow[rg*4+q]=1.f/s;
    }
    __syncthreads();
    for (int i=tid;i<32*256;i+=256){
        int r=i>>8, c=i&255;
        float v = (c<32) ? sxm[r*32+c] : su[r*320 + 57 + c];
        xout[(long long)(b0+r)*256 + c] = v*srow[r];
    }
}

// -------- dense head: output1/2, output1_new/2_new, x_temp --------
__global__ void __launch_bounds__(128) k_dense(
    const float* __restrict__ xin, const float* __restrict__ sent,
    const float* __restrict__ Ws1, const float* __restrict__ bs1,
    const float* __restrict__ Ws2, const float* __restrict__ bs2,
    const float* __restrict__ Wf1, const float* __restrict__ bf1,
    const float* __restrict__ Wfa, const float* __restrict__ bfa,
    const float* __restrict__ Wfb, const float* __restrict__ bfb,
    float* __restrict__ o1n, float* __restrict__ o2n, float* __restrict__ xt)
{
    __shared__ float so1[32*128];   // [j][r] col-major
    __shared__ float so2[32*128];
    __shared__ float buf[4096];     // k-tiles (64x36) then relu(t) [j][r]
    const int b0 = blockIdx.x*32;
    const int tid = threadIdx.x;
    float acc[32];

    // output2 = sent @ Ws2 + bs2
    #pragma unroll
    for (int r=0;r<32;r++) acc[r]=0.f;
    for (int k0=0;k0<EE2;k0+=64){
        __syncthreads();
        for (int i=tid;i<2048;i+=128){
            int r=i>>6, kk=i&63;
            buf[kk*36+r] = sent[(long long)(b0+r)*EE2 + (k0+kk)];
        }
        __syncthreads();
        #pragma unroll 2
        for (int kk=0;kk<64;kk++){
            float wv = Ws2[(k0+kk)*128 + tid];
            const float4* pv = reinterpret_cast<const float4*>(&buf[kk*36]);
            #pragma unroll
            for (int q=0;q<8;q++){
                float4 v = pv[q];
                acc[4*q+0]=fmaf(v.x,wv,acc[4*q+0]);
                acc[4*q+1]=fmaf(v.y,wv,acc[4*q+1]);
                acc[4*q+2]=fmaf(v.z,wv,acc[4*q+2]);
                acc[4*q+3]=fmaf(v.w,wv,acc[4*q+3]);
            }
        }
    }
    {
        float bb = bs2[tid];
        #pragma unroll
        for (int r=0;r<32;r++) so2[tid*32+r] = acc[r]+bb;
    }

    // output1 = x @ Ws1 + bs1
    #pragma unroll
    for (int r=0;r<32;r++) acc[r]=0.f;
    for (int k0=0;k0<256;k0+=64){
        __syncthreads();
        for (int i=tid;i<2048;i+=128){
            int r=i>>6, kk=i&63;
            buf[kk*36+r] = xin[(long long)(b0+r)*256 + (k0+kk)];
        }
        __syncthreads();
        #pragma unroll 2
        for (int kk=0;kk<64;kk++){
            float wv = Ws1[(k0+kk)*128 + tid];
            const float4* pv = reinterpret_cast<const float4*>(&buf[kk*36]);
            #pragma unroll
            for (int q=0;q<8;q++){
                float4 v = pv[q];
                acc[4*q+0]=fmaf(v.x,wv,acc[4*q+0]);
                acc[4*q+1]=fmaf(v.y,wv,acc[4*q+1]);
                acc[4*q+2]=fmaf(v.z,wv,acc[4*q+2]);
                acc[4*q+3]=fmaf(v.w,wv,acc[4*q+3]);
            }
        }
    }
    {
        float bb = bs1[tid];
        #pragma unroll
        for (int r=0;r<32;r++) so1[tid*32+r] = acc[r]+bb;
    }
    __syncthreads();

    // o1n = output1 @ Wf1 + bf1 ; o2n = output2 @ Wf1 + bf1
    {
        const int j2 = tid & 63;
        const int half = tid >> 6;
        float a1[16], a2[16];
        #pragma unroll
        for (int q=0;q<16;q++){ a1[q]=0.f; a2[q]=0.f; }
        for (int k=0;k<128;k++){
            float wv = Wf1[k*64+j2];
            const float4* p1 = reinterpret_cast<const float4*>(&so1[k*32 + half*16]);
            const float4* p2 = reinterpret_cast<const float4*>(&so2[k*32 + half*16]);
            #pragma unroll
            for (int q=0;q<4;q++){
                float4 v1=p1[q], v2=p2[q];
                a1[4*q+0]=fmaf(v1.x,wv,a1[4*q+0]); a2[4*q+0]=fmaf(v2.x,wv,a2[4*q+0]);
                a1[4*q+1]=fmaf(v1.y,wv,a1[4*q+1]); a2[4*q+1]=fmaf(v2.y,wv,a2[4*q+1]);
                a1[4*q+2]=fmaf(v1.z,wv,a1[4*q+2]); a2[4*q+2]=fmaf(v2.z,wv,a2[4*q+2]);
                a1[4*q+3]=fmaf(v1.w,wv,a1[4*q+3]); a2[4*q+3]=fmaf(v2.w,wv,a2[4*q+3]);
            }
        }
        float bb = bf1[j2];
        #pragma unroll
        for (int q=0;q<16;q++){
            int r = half*16+q;
            o1n[(long long)(b0+r)*64 + j2] = a1[q]+bb;
            o2n[(long long)(b0+r)*64 + j2] = a2[q]+bb;
        }
    }

    // t = relu(concat(output1,output2) @ Wfa + bfa)
    #pragma unroll
    for (int r=0;r<32;r++) acc[r]=0.f;
    for (int k=0;k<128;k++){
        float wv = Wfa[k*128+tid];
        const float4* pv = reinterpret_cast<const float4*>(&so1[k*32]);
        #pragma unroll
        for (int q=0;q<8;q++){
            float4 v = pv[q];
            acc[4*q+0]=fmaf(v.x,wv,acc[4*q+0]);
            acc[4*q+1]=fmaf(v.y,wv,acc[4*q+1]);
            acc[4*q+2]=fmaf(v.z,wv,acc[4*q+2]);
            acc[4*q+3]=fmaf(v.w,wv,acc[4*q+3]);
        }
    }
    for (int k=0;k<128;k++){
        float wv = Wfa[(128+k)*128+tid];
        const float4* pv = reinterpret_cast<const float4*>(&so2[k*32]);
        #pragma unroll
        for (int q=0;q<8;q++){
            float4 v = pv[q];
            acc[4*q+0]=fmaf(v.x,wv,acc[4*q+0]);
            acc[4*q+1]=fmaf(v.y,wv,acc[4*q+1]);
            acc[4*q+2]=fmaf(v.z,wv,acc[4*q+2]);
            acc[4*q+3]=fmaf(v.w,wv,acc[4*q+3]);
        }
    }
    __syncthreads();
    {
        float bb = bfa[tid];
        float4* stp = reinterpret_cast<float4*>(&buf[tid*32]);
        #pragma unroll
        for (int q=0;q<8;q++){
            float4 v;
            v.x = fmaxf(acc[4*q+0]+bb, 0.f);
            v.y = fmaxf(acc[4*q+1]+bb, 0.f);
            v.z = fmaxf(acc[4*q+2]+bb, 0.f);
            v.w = fmaxf(acc[4*q+3]+bb, 0.f);
            stp[q]=v;
        }
    }
    __syncthreads();
    // x_temp = t @ Wfb + bfb
    for (int i=tid;i<160;i+=128){
        int r=i/5, c=i%5;
        float s = bfb[c];
        for (int j=0;j<128;j++) s = fmaf(buf[j*32+r], Wfb[j*5+c], s);
        xt[(long long)(b0+r)*5 + c] = s;
    }
}

extern "C" void kernel_launch(void* const* d_in, const int* in_sizes, int n_in,
                              void* d_out, int out_size)
{
    (void)in_sizes; (void)n_in; (void)out_size;
    const float* pern  = (const float*)d_in[0];
    const float* wordf = (const float*)d_in[1];
    const int*   padj  = (const int*)d_in[2];
    const int*   wpadj = (const int*)d_in[3];
    const float* uwa   = (const float*)d_in[4];
    const float* sent  = (const float*)d_in[5];
    const float* w1    = (const float*)d_in[6];
    const float* as1   = (const float*)d_in[7];
    const float* ad1   = (const float*)d_in[8];
    const float* b1    = (const float*)d_in[9];
    const float* w2    = (const float*)d_in[10];
    const float* as2   = (const float*)d_in[11];
    const float* ad2   = (const float*)d_in[12];
    const float* b2    = (const float*)d_in[13];
    const float* Ws1   = (const float*)d_in[14];
    const float* bs1   = (const float*)d_in[15];
    const float* Ws2   = (const float*)d_in[16];
    const float* bs2   = (const float*)d_in[17];
    const float* Wf1   = (const float*)d_in[18];
    const float* bf1   = (const float*)d_in[19];
    const float* Wfa   = (const float*)d_in[20];
    const float* bfa   = (const float*)d_in[21];
    const float* Wfb   = (const float*)d_in[22];
    const float* bfb   = (const float*)d_in[23];
    float* out = (float*)d_out;

    cudaFuncSetAttribute(k_hp<0>,  cudaFuncAttributeMaxDynamicSharedMemorySize, 65536);
    cudaFuncSetAttribute(k_hp<1>,  cudaFuncAttributeMaxDynamicSharedMemorySize, 65536);
    cudaFuncSetAttribute(k_attn<0>,cudaFuncAttributeMaxDynamicSharedMemorySize, 8*NP*4);
    cudaFuncSetAttribute(k_attn<1>,cudaFuncAttributeMaxDynamicSharedMemorySize, 8*NA*4);
    cudaFuncSetAttribute(k_x2,     cudaFuncAttributeMaxDynamicSharedMemorySize, 60000);

    k_copy_word<<<(NW*FF+255)/256, 256>>>(wordf);
    k_hp<0><<<dim3(NP/32, HH), 256, 65536>>>(pern, w1, as1, ad1);
    k_attn<0><<<dim3(HH, NP/8), 256, 8*NP*4>>>(padj, out+OFF_APP, b1);
    k_hp<1><<<dim3((NA+31)/32, HH), 256, 65536>>>(pern, w2, as2, ad2);
    k_attn<1><<<dim3(HH, (NA+7)/8), 256, 8*NA*4>>>(wpadj, out+OFF_AWP, b2);
    k_mean<<<(NW*OO+255)/256, 256>>>();
    k_x2<<<BB/32, 256, (32*320 + NW*OO + 1024 + 32)*4>>>(uwa, out+OFF_X);
    k_dense<<<BB/32, 128>>>(out+OFF_X, sent, Ws1,bs1,Ws2,bs2,Wf1,bf1,Wfa,bfa,Wfb,bfb,
                            out+OFF_O1N, out+OFF_O2N, out+OFF_XT);
}

// round 6
// speedup vs baseline: 1.3811x; 1.0005x over previous
#include <cuda_runtime.h>
#include <math.h>

#define NP 2048
#define NW 89
#define NA 2137
#define BB 16384
#define EE2 768
#define UWD 313
#define HH 8
#define FF 256
#define OO 32

// output layout: concat of flattened outputs in reference return order
#define OFF_O1N 0LL                 // (B,64)
#define OFF_O2N 1048576LL           // (B,64)
#define OFF_XT  2097152LL           // (B,5)
#define OFF_APP 2179072LL           // (8,2048,2048)
#define OFF_AWP 35733504LL          // (8,2137,2137)
#define OFF_X   72267656LL          // (B,256)

// -------- scratch (no allocations allowed -> device globals) --------
__device__ float g_hp1[HH*NP*OO];
__device__ float g_es1[HH*NP];
__device__ float g_ed1[HH*NP];
__device__ float g_h1wp[NA*FF];
__device__ float g_hp2[HH*NA*OO];
__device__ float g_es2[HH*NA];
__device__ float g_ed2[HH*NA];
__device__ float g_out2[HH*NW*OO];
__device__ float g_h2w[NW*OO];

// -------- copy word features into top of h1_wp --------
__global__ void k_copy_word(const float* __restrict__ wf){
    int i = blockIdx.x*blockDim.x + threadIdx.x;
    if (i < NW*FF) g_h1wp[i] = wf[i];
}

// -------- hp = einsum('nf,hfo->hno'), plus e_src/e_dst --------
// one block = (32 rows, 1 head). 256 threads = 32 cols x 8 row-groups, 4 rows/thread.
template<int SEL>
__global__ void __launch_bounds__(256) k_hp(const float* __restrict__ hin,
        const float* __restrict__ w, const float* __restrict__ asrc,
        const float* __restrict__ adst)
{
    constexpr int N = SEL ? NA : NP;
    const float* h  = SEL ? g_h1wp : hin;
    float* hp = SEL ? g_hp2 : g_hp1;
    float* es = SEL ? g_es2 : g_es1;
    float* ed = SEL ? g_ed2 : g_ed1;

    extern __shared__ float sm[];
    float* sw = sm;          // [256][32] this head's weight slice
    float* sh = sm + 8192;   // [32][256] row tile

    const int hd = blockIdx.y;
    const int b0 = blockIdx.x*32;
    const int tid = threadIdx.x;

    {
        const float4* src = reinterpret_cast<const float4*>(w + hd*FF*OO);
        float4* dst = reinterpret_cast<float4*>(sw);
        #pragma unroll
        for (int i=0;i<8;i++) dst[tid + i*256] = src[tid + i*256];
    }
    for (int i=tid;i<2048;i+=256){
        int r=i>>6, c4=i&63;
        int n=b0+r;
        float4 v = make_float4(0.f,0.f,0.f,0.f);
        if (n<N) v = *reinterpret_cast<const float4*>(h + (long long)n*FF + c4*4);
        *reinterpret_cast<float4*>(&sh[r*256 + c4*4]) = v;
    }
    __syncthreads();

    const int o = tid&31, rg = tid>>5;
    float acc[4] = {0.f,0.f,0.f,0.f};
    const float* shr = sh + rg*4*256;
    #pragma unroll 2
    for (int k0=0;k0<256;k0+=4){
        float w0=sw[(k0+0)*32+o], w1=sw[(k0+1)*32+o];
        float w2=sw[(k0+2)*32+o], w3=sw[(k0+3)*32+o];
        #pragma unroll
        for (int q=0;q<4;q++){
            float4 hv = *reinterpret_cast<const float4*>(&shr[q*256+k0]);
            acc[q]=fmaf(hv.x,w0,acc[q]);
            acc[q]=fmaf(hv.y,w1,acc[q]);
            acc[q]=fmaf(hv.z,w2,acc[q]);
            acc[q]=fmaf(hv.w,w3,acc[q]);
        }
    }
    float av = asrc[hd*32+o];
    float dv = adst[hd*32+o];
    #pragma unroll
    for (int q=0;q<4;q++){
        int n=b0+rg*4+q;
        if (n<N) hp[((long long)hd*N+n)*OO+o]=acc[q];
        float s=acc[q]*av, d=acc[q]*dv;
        #pragma unroll
        for (int off=16;off;off>>=1){
            s+=__shfl_xor_sync(0xffffffffu,s,off);
            d+=__shfl_xor_sync(0xffffffffu,d,off);
        }
        if (o==0 && n<N){ es[hd*N+n]=s; ed[hd*N+n]=d; }
    }
}

// -------- attention: softmax rows + fused attn@hp --------
// grid = (heads, rowgroups): the 8 heads of one rowgroup are ADJACENT block ids
// so the adjacency rows are fetched from DRAM once and hit L2 for the other 7.
template<int SEL>
__global__ void __launch_bounds__(256) k_attn(const int* __restrict__ adj,
        float* __restrict__ attn, const float* __restrict__ bias)
{
    constexpr int N = SEL ? NA : NP;
    const float* hp = SEL ? g_hp2 : g_hp1;
    const float* es = SEL ? g_es2 : g_es1;
    const float* ed = SEL ? g_ed2 : g_ed1;

    extern __shared__ float p[];            // 8*N floats
    __shared__ float red[8];
    __shared__ float sinv[8];
    __shared__ float red2[2048];

    const int hd = blockIdx.x;
    const int n0 = blockIdx.y*8;
    const int tid = threadIdx.x;
    const float* edr = ed + hd*N;

    for (int r=0;r<8;r++){
        int n = n0+r;
        if (n>=N) break;                    // uniform across block
        float esn = es[hd*N+n];
        const int* arow = adj + (long long)n*N;
        float* pr = p + r*N;
        float mx = -3.0e38f;
        for (int m=tid;m<N;m+=256){
            float v = esn + edr[m];
            v = v>0.f ? v : 0.2f*v;         // leaky_relu 0.2
            if (arow[m]==0) v = -1.0e9f;
            pr[m]=v;
            mx = fmaxf(mx,v);
        }
        #pragma unroll
        for (int off=16;off;off>>=1) mx = fmaxf(mx,__shfl_xor_sync(0xffffffffu,mx,off));
        if ((tid&31)==0) red[tid>>5]=mx;
        __syncthreads();
        if (tid==0){
            float v=red[0];
            #pragma unroll
            for (int i=1;i<8;i++) v=fmaxf(v,red[i]);
            red[0]=v;
        }
        __syncthreads();
        float Mx = red[0];
        float sm = 0.f;
        for (int m=tid;m<N;m+=256){
            float q = __expf(pr[m]-Mx);
            pr[m]=q;
            sm+=q;
        }
        __syncthreads();
        #pragma unroll
        for (int off=16;off;off>>=1) sm += __shfl_xor_sync(0xffffffffu,sm,off);
        if ((tid&31)==0) red[tid>>5]=sm;
        __syncthreads();
        if (tid==0){
            float v=0.f;
            #pragma unroll
            for (int i=0;i<8;i++) v+=red[i];
            sinv[r]=1.f/v;
        }
        __syncthreads();
        float iv = sinv[r];
        float* ar = attn + ((long long)(hd*N+n))*N;
        for (int m=tid;m<N;m+=256) ar[m] = pr[m]*iv;
        __syncthreads();
    }

    // attn @ hp : GAT1 needs every row; GAT2 only rows n<89 (only h2_word is used)
    if (SEL==0 || n0 < NW){
        const int ml = tid>>5, o = tid&31;
        float acc[8];
        #pragma unroll
        for (int r=0;r<8;r++) acc[r]=0.f;
        const float* hpb = hp + (long long)hd*N*OO + o;
        for (int m=ml;m<N;m+=8){
            float hv = hpb[(long long)m*OO];
            #pragma unroll
            for (int r=0;r<8;r++) acc[r] = fmaf(p[r*N+m], hv, acc[r]);
        }
        #pragma unroll
        for (int r=0;r<8;r++) red2[r*256+tid]=acc[r];
        __syncthreads();
        const int rr = tid>>5;
        const int n = n0+rr;
        float v = 0.f;
        #pragma unroll
        for (int m2=0;m2<8;m2++) v += red2[rr*256 + m2*32 + o];
        if (n < N){
            v = v*sinv[rr] + bias[o];
            if (SEL==0){
                g_h1wp[(long long)(NW+n)*FF + hd*OO + o] = (v>0.f) ? v : expm1f(v);
            } else if (n < NW){
                g_out2[(hd*NW+n)*OO + o] = v;
            }
        }
    }
}

// -------- mean over heads for h2_word --------
__global__ void k_mean(){
    int i = blockIdx.x*blockDim.x + threadIdx.x;
    if (i < NW*OO){
        float s=0.f;
        #pragma unroll
        for (int h=0;h<HH;h++) s += g_out2[h*NW*OO + i];
        g_h2w[i] = s*0.125f;
    }
}

// -------- x = normalize(concat(uwa[:, :89] @ h2_word, uwa[:, 89:])) --------
// 32 rows per block (512 blocks): h2w loaded once per block instead of per row.
__global__ void __launch_bounds__(256) k_x2(const float* __restrict__ uwa,
                                            float* __restrict__ xout)
{
    extern __shared__ float sm[];
    float* su   = sm;              // [32][320]
    float* sh2  = sm + 32*320;     // [89][32]
    float* sxm  = sh2 + NW*OO;     // [32][32]
    float* srow = sxm + 1024;      // [32] reciprocal row sums

    const int b0 = blockIdx.x*32;
    const int tid = threadIdx.x;

    for (int i=tid;i<NW*OO;i+=256) sh2[i]=g_h2w[i];
    for (int i=tid;i<32*UWD;i+=256){
        int r=i/UWD, w=i-r*UWD;
        su[r*320+w]=uwa[(long long)(b0+r)*UWD + w];
    }
    __syncthreads();

    const int o = tid&31, rg = tid>>5;
    float acc[4]={0.f,0.f,0.f,0.f};
    for (int w=0;w<NW;w++){
        float hv = sh2[w*32+o];
        #pragma unroll
        for (int q=0;q<4;q++) acc[q]=fmaf(su[(rg*4+q)*320+w], hv, acc[q]);
    }
    float ts[4]={0.f,0.f,0.f,0.f};
    for (int w=NW+o; w<UWD; w+=32){
        #pragma unroll
        for (int q=0;q<4;q++) ts[q]+=su[(rg*4+q)*320+w];
    }
    #pragma unroll
    for (int q=0;q<4;q++){
        sxm[(rg*4+q)*32+o]=acc[q];
        float s = acc[q]+ts[q];
        #pragma unroll
        for (int off=16;off;off>>=1) s += __shfl_xor_sync(0xffffffffu,s,off);
        if (o==0) srow[rg*4+q]=1.f/s;
    }
    __syncthreads();
    for (int i=tid;i<32*256;i+=256){
        int r=i>>8, c=i&255;
        float v = (c<32) ? sxm[r*32+c] : su[r*320 + 57 + c];
        xout[(long long)(b0+r)*256 + c] = v*srow[r];
    }
}

// -------- dense head: output1/2, output1_new/2_new, x_temp --------
__global__ void __launch_bounds__(128) k_dense(
    const float* __restrict__ xin, const float* __restrict__ sent,
    const float* __restrict__ Ws1, const float* __restrict__ bs1,
    const float* __restrict__ Ws2, const float* __restrict__ bs2,
    const float* __restrict__ Wf1, const float* __restrict__ bf1,
    const float* __restrict__ Wfa, const float* __restrict__ bfa,
    const float* __restrict__ Wfb, const float* __restrict__ bfb,
    float* __restrict__ o1n, float* __restrict__ o2n, float* __restrict__ xt)
{
    __shared__ float so1[32*128];   // [j][r] col-major
    __shared__ float so2[32*128];
    __shared__ float buf[4096];     // k-tiles (64x36) then relu(t) [j][r]
    const int b0 = blockIdx.x*32;
    const int tid = threadIdx.x;
    float acc[32];

    // output2 = sent @ Ws2 + bs2
    #pragma unroll
    for (int r=0;r<32;r++) acc[r]=0.f;
    for (int k0=0;k0<EE2;k0+=64){
        __syncthreads();
        for (int i=tid;i<2048;i+=128){
            int r=i>>6, kk=i&63;
            buf[kk*36+r] = sent[(long long)(b0+r)*EE2 + (k0+kk)];
        }
        __syncthreads();
        #pragma unroll 2
        for (int kk=0;kk<64;kk++){
            float wv = Ws2[(k0+kk)*128 + tid];
            const float4* pv = reinterpret_cast<const float4*>(&buf[kk*36]);
            #pragma unroll
            for (int q=0;q<8;q++){
                float4 v = pv[q];
                acc[4*q+0]=fmaf(v.x,wv,acc[4*q+0]);
                acc[4*q+1]=fmaf(v.y,wv,acc[4*q+1]);
                acc[4*q+2]=fmaf(v.z,wv,acc[4*q+2]);
                acc[4*q+3]=fmaf(v.w,wv,acc[4*q+3]);
            }
        }
    }
    {
        float bb = bs2[tid];
        #pragma unroll
        for (int r=0;r<32;r++) so2[tid*32+r] = acc[r]+bb;
    }

    // output1 = x @ Ws1 + bs1
    #pragma unroll
    for (int r=0;r<32;r++) acc[r]=0.f;
    for (int k0=0;k0<256;k0+=64){
        __syncthreads();
        for (int i=tid;i<2048;i+=128){
            int r=i>>6, kk=i&63;
            buf[kk*36+r] = xin[(long long)(b0+r)*256 + (k0+kk)];
        }
        __syncthreads();
        #pragma unroll 2
        for (int kk=0;kk<64;kk++){
            float wv = Ws1[(k0+kk)*128 + tid];
            const float4* pv = reinterpret_cast<const float4*>(&buf[kk*36]);
            #pragma unroll
            for (int q=0;q<8;q++){
                float4 v = pv[q];
                acc[4*q+0]=fmaf(v.x,wv,acc[4*q+0]);
                acc[4*q+1]=fmaf(v.y,wv,acc[4*q+1]);
                acc[4*q+2]=fmaf(v.z,wv,acc[4*q+2]);
                acc[4*q+3]=fmaf(v.w,wv,acc[4*q+3]);
            }
        }
    }
    {
        float bb = bs1[tid];
        #pragma unroll
        for (int r=0;r<32;r++) so1[tid*32+r] = acc[r]+bb;
    }
    __syncthreads();

    // o1n = output1 @ Wf1 + bf1 ; o2n = output2 @ Wf1 + bf1
    {
        const int j2 = tid & 63;
        const int half = tid >> 6;
        float a1[16], a2[16];
        #pragma unroll
        for (int q=0;q<16;q++){ a1[q]=0.f; a2[q]=0.f; }
        for (int k=0;k<128;k++){
            float wv = Wf1[k*64+j2];
            const float4* p1 = reinterpret_cast<const float4*>(&so1[k*32 + half*16]);
            const float4* p2 = reinterpret_cast<const float4*>(&so2[k*32 + half*16]);
            #pragma unroll
            for (int q=0;q<4;q++){
                float4 v1=p1[q], v2=p2[q];
                a1[4*q+0]=fmaf(v1.x,wv,a1[4*q+0]); a2[4*q+0]=fmaf(v2.x,wv,a2[4*q+0]);
                a1[4*q+1]=fmaf(v1.y,wv,a1[4*q+1]); a2[4*q+1]=fmaf(v2.y,wv,a2[4*q+1]);
                a1[4*q+2]=fmaf(v1.z,wv,a1[4*q+2]); a2[4*q+2]=fmaf(v2.z,wv,a2[4*q+2]);
                a1[4*q+3]=fmaf(v1.w,wv,a1[4*q+3]); a2[4*q+3]=fmaf(v2.w,wv,a2[4*q+3]);
            }
        }
        float bb = bf1[j2];
        #pragma unroll
        for (int q=0;q<16;q++){
            int r = half*16+q;
            o1n[(long long)(b0+r)*64 + j2] = a1[q]+bb;
            o2n[(long long)(b0+r)*64 + j2] = a2[q]+bb;
        }
    }

    // t = relu(concat(output1,output2) @ Wfa + bfa)
    #pragma unroll
    for (int r=0;r<32;r++) acc[r]=0.f;
    for (int k=0;k<128;k++){
        float wv = Wfa[k*128+tid];
        const float4* pv = reinterpret_cast<const float4*>(&so1[k*32]);
        #pragma unroll
        for (int q=0;q<8;q++){
            float4 v = pv[q];
            acc[4*q+0]=fmaf(v.x,wv,acc[4*q+0]);
            acc[4*q+1]=fmaf(v.y,wv,acc[4*q+1]);
            acc[4*q+2]=fmaf(v.z,wv,acc[4*q+2]);
            acc[4*q+3]=fmaf(v.w,wv,acc[4*q+3]);
        }
    }
    for (int k=0;k<128;k++){
        float wv = Wfa[(128+k)*128+tid];
        const float4* pv = reinterpret_cast<const float4*>(&so2[k*32]);
        #pragma unroll
        for (int q=0;q<8;q++){
            float4 v = pv[q];
            acc[4*q+0]=fmaf(v.x,wv,acc[4*q+0]);
            acc[4*q+1]=fmaf(v.y,wv,acc[4*q+1]);
            acc[4*q+2]=fmaf(v.z,wv,acc[4*q+2]);
            acc[4*q+3]=fmaf(v.w,wv,acc[4*q+3]);
        }
    }
    __syncthreads();
    {
        float bb = bfa[tid];
        float4* stp = reinterpret_cast<float4*>(&buf[tid*32]);
        #pragma unroll
        for (int q=0;q<8;q++){
            float4 v;
            v.x = fmaxf(acc[4*q+0]+bb, 0.f);
            v.y = fmaxf(acc[4*q+1]+bb, 0.f);
            v.z = fmaxf(acc[4*q+2]+bb, 0.f);
            v.w = fmaxf(acc[4*q+3]+bb, 0.f);
            stp[q]=v;
        }
    }
    __syncthreads();
    // x_temp = t @ Wfb + bfb
    for (int i=tid;i<160;i+=128){
        int r=i/5, c=i%5;
        float s = bfb[c];
        for (int j=0;j<128;j++) s = fmaf(buf[j*32+r], Wfb[j*5+c], s);
        xt[(long long)(b0+r)*5 + c] = s;
    }
}

extern "C" void kernel_launch(void* const* d_in, const int* in_sizes, int n_in,
                              void* d_out, int out_size)
{
    (void)in_sizes; (void)n_in; (void)out_size;
    const float* pern  = (const float*)d_in[0];
    const float* wordf = (const float*)d_in[1];
    const int*   padj  = (const int*)d_in[2];
    const int*   wpadj = (const int*)d_in[3];
    const float* uwa   = (const float*)d_in[4];
    const float* sent  = (const float*)d_in[5];
    const float* w1    = (const float*)d_in[6];
    const float* as1   = (const float*)d_in[7];
    const float* ad1   = (const float*)d_in[8];
    const float* b1    = (const float*)d_in[9];
    const float* w2    = (const float*)d_in[10];
    const float* as2   = (const float*)d_in[11];
    const float* ad2   = (const float*)d_in[12];
    const float* b2    = (const float*)d_in[13];
    const float* Ws1   = (const float*)d_in[14];
    const float* bs1   = (const float*)d_in[15];
    const float* Ws2   = (const float*)d_in[16];
    const float* bs2   = (const float*)d_in[17];
    const float* Wf1   = (const float*)d_in[18];
    const float* bf1   = (const float*)d_in[19];
    const float* Wfa   = (const float*)d_in[20];
    const float* bfa   = (const float*)d_in[21];
    const float* Wfb   = (const float*)d_in[22];
    const float* bfb   = (const float*)d_in[23];
    float* out = (float*)d_out;

    cudaFuncSetAttribute(k_hp<0>,  cudaFuncAttributeMaxDynamicSharedMemorySize, 65536);
    cudaFuncSetAttribute(k_hp<1>,  cudaFuncAttributeMaxDynamicSharedMemorySize, 65536);
    cudaFuncSetAttribute(k_attn<0>,cudaFuncAttributeMaxDynamicSharedMemorySize, 8*NP*4);
    cudaFuncSetAttribute(k_attn<1>,cudaFuncAttributeMaxDynamicSharedMemorySize, 8*NA*4);
    cudaFuncSetAttribute(k_x2,     cudaFuncAttributeMaxDynamicSharedMemorySize, 60000);

    k_copy_word<<<(NW*FF+255)/256, 256>>>(wordf);
    k_hp<0><<<dim3(NP/32, HH), 256, 65536>>>(pern, w1, as1, ad1);
    k_attn<0><<<dim3(HH, NP/8), 256, 8*NP*4>>>(padj, out+OFF_APP, b1);
    k_hp<1><<<dim3((NA+31)/32, HH), 256, 65536>>>(pern, w2, as2, ad2);
    k_attn<1><<<dim3(HH, (NA+7)/8), 256, 8*NA*4>>>(wpadj, out+OFF_AWP, b2);
    k_mean<<<(NW*OO+255)/256, 256>>>();
    k_x2<<<BB/32, 256, (32*320 + NW*OO + 1024 + 32)*4>>>(uwa, out+OFF_X);
    k_dense<<<BB/32, 128>>>(out+OFF_X, sent, Ws1,bs1,Ws2,bs2,Wf1,bf1,Wfa,bfa,Wfb,bfb,
                            out+OFF_O1N, out+OFF_O2N, out+OFF_XT);
}

// round 7
// speedup vs baseline: 1.3816x; 1.0003x over previous
#include <cuda_runtime.h>
#include <math.h>

#define NP 2048
#define NW 89
#define NA 2137
#define BB 16384
#define EE2 768
#define UWD 313
#define HH 8
#define FF 256
#define OO 32

// output layout: concat of flattened outputs in reference return order
#define OFF_O1N 0LL                 // (B,64)
#define OFF_O2N 1048576LL           // (B,64)
#define OFF_XT  2097152LL           // (B,5)
#define OFF_APP 2179072LL           // (8,2048,2048)
#define OFF_AWP 35733504LL          // (8,2137,2137)
#define OFF_X   72267656LL          // (B,256)

// -------- scratch (no allocations allowed -> device globals) --------
__device__ float g_hp1[HH*NP*OO];
__device__ float g_es1[HH*NP];
__device__ float g_ed1[HH*NP];
__device__ float g_h1wp[NA*FF];
__device__ float g_hp2[HH*NA*OO];
__device__ float g_es2[HH*NA];
__device__ float g_ed2[HH*NA];
__device__ float g_out2[HH*NW*OO];
__device__ float g_h2w[NW*OO];

// -------- copy word features into top of h1_wp --------
__global__ void k_copy_word(const float* __restrict__ wf){
    int i = blockIdx.x*blockDim.x + threadIdx.x;
    if (i < NW*FF) g_h1wp[i] = wf[i];
}

// -------- hp = einsum('nf,hfo->hno'), plus e_src/e_dst --------
// one block = (32 rows, 1 head). 256 threads = 32 cols x 8 row-groups, 4 rows/thread.
template<int SEL>
__global__ void __launch_bounds__(256) k_hp(const float* __restrict__ hin,
        const float* __restrict__ w, const float* __restrict__ asrc,
        const float* __restrict__ adst)
{
    constexpr int N = SEL ? NA : NP;
    const float* h  = SEL ? g_h1wp : hin;
    float* hp = SEL ? g_hp2 : g_hp1;
    float* es = SEL ? g_es2 : g_es1;
    float* ed = SEL ? g_ed2 : g_ed1;

    extern __shared__ float sm[];
    float* sw = sm;          // [256][32] this head's weight slice
    float* sh = sm + 8192;   // [32][256] row tile

    const int hd = blockIdx.y;
    const int b0 = blockIdx.x*32;
    const int tid = threadIdx.x;

    {
        const float4* src = reinterpret_cast<const float4*>(w + hd*FF*OO);
        float4* dst = reinterpret_cast<float4*>(sw);
        #pragma unroll
        for (int i=0;i<8;i++) dst[tid + i*256] = src[tid + i*256];
    }
    for (int i=tid;i<2048;i+=256){
        int r=i>>6, c4=i&63;
        int n=b0+r;
        float4 v = make_float4(0.f,0.f,0.f,0.f);
        if (n<N) v = *reinterpret_cast<const float4*>(h + (long long)n*FF + c4*4);
        *reinterpret_cast<float4*>(&sh[r*256 + c4*4]) = v;
    }
    __syncthreads();

    const int o = tid&31, rg = tid>>5;
    float acc[4] = {0.f,0.f,0.f,0.f};
    const float* shr = sh + rg*4*256;
    #pragma unroll 2
    for (int k0=0;k0<256;k0+=4){
        float w0=sw[(k0+0)*32+o], w1=sw[(k0+1)*32+o];
        float w2=sw[(k0+2)*32+o], w3=sw[(k0+3)*32+o];
        #pragma unroll
        for (int q=0;q<4;q++){
            float4 hv = *reinterpret_cast<const float4*>(&shr[q*256+k0]);
            acc[q]=fmaf(hv.x,w0,acc[q]);
            acc[q]=fmaf(hv.y,w1,acc[q]);
            acc[q]=fmaf(hv.z,w2,acc[q]);
            acc[q]=fmaf(hv.w,w3,acc[q]);
        }
    }
    float av = asrc[hd*32+o];
    float dv = adst[hd*32+o];
    #pragma unroll
    for (int q=0;q<4;q++){
        int n=b0+rg*4+q;
        if (n<N) hp[((long long)hd*N+n)*OO+o]=acc[q];
        float s=acc[q]*av, d=acc[q]*dv;
        #pragma unroll
        for (int off=16;off;off>>=1){
            s+=__shfl_xor_sync(0xffffffffu,s,off);
            d+=__shfl_xor_sync(0xffffffffu,d,off);
        }
        if (o==0 && n<N){ es[hd*N+n]=s; ed[hd*N+n]=d; }
    }
}

// -------- attention: softmax rows + fused attn@hp --------
// grid = (heads, rowgroups): the 8 heads of one rowgroup are ADJACENT block ids
// so the adjacency rows are fetched from DRAM once and hit L2 for the other 7.
template<int SEL>
__global__ void __launch_bounds__(256) k_attn(const int* __restrict__ adj,
        float* __restrict__ attn, const float* __restrict__ bias)
{
    constexpr int N = SEL ? NA : NP;
    const float* hp = SEL ? g_hp2 : g_hp1;
    const float* es = SEL ? g_es2 : g_es1;
    const float* ed = SEL ? g_ed2 : g_ed1;

    extern __shared__ float p[];            // 8*N floats
    __shared__ float red[8];
    __shared__ float sinv[8];
    __shared__ float red2[2048];

    const int hd = blockIdx.x;
    const int n0 = blockIdx.y*8;
    const int tid = threadIdx.x;
    const float* edr = ed + hd*N;

    for (int r=0;r<8;r++){
        int n = n0+r;
        if (n>=N) break;                    // uniform across block
        float esn = es[hd*N+n];
        const int* arow = adj + (long long)n*N;
        float* pr = p + r*N;
        float mx = -3.0e38f;
        for (int m=tid;m<N;m+=256){
            float v = esn + edr[m];
            v = v>0.f ? v : 0.2f*v;         // leaky_relu 0.2
            if (arow[m]==0) v = -1.0e9f;
            pr[m]=v;
            mx = fmaxf(mx,v);
        }
        #pragma unroll
        for (int off=16;off;off>>=1) mx = fmaxf(mx,__shfl_xor_sync(0xffffffffu,mx,off));
        if ((tid&31)==0) red[tid>>5]=mx;
        __syncthreads();
        if (tid==0){
            float v=red[0];
            #pragma unroll
            for (int i=1;i<8;i++) v=fmaxf(v,red[i]);
            red[0]=v;
        }
        __syncthreads();
        float Mx = red[0];
        float sm = 0.f;
        for (int m=tid;m<N;m+=256){
            float q = __expf(pr[m]-Mx);
            pr[m]=q;
            sm+=q;
        }
        __syncthreads();
        #pragma unroll
        for (int off=16;off;off>>=1) sm += __shfl_xor_sync(0xffffffffu,sm,off);
        if ((tid&31)==0) red[tid>>5]=sm;
        __syncthreads();
        if (tid==0){
            float v=0.f;
            #pragma unroll
            for (int i=0;i<8;i++) v+=red[i];
            sinv[r]=1.f/v;
        }
        __syncthreads();
        float iv = sinv[r];
        float* ar = attn + ((long long)(hd*N+n))*N;
        for (int m=tid;m<N;m+=256) ar[m] = pr[m]*iv;
        __syncthreads();
    }

    // attn @ hp : GAT1 needs every row; GAT2 only rows n<89 (only h2_word is used)
    if (SEL==0 || n0 < NW){
        const int ml = tid>>5, o = tid&31;
        float acc[8];
        #pragma unroll
        for (int r=0;r<8;r++) acc[r]=0.f;
        const float* hpb = hp + (long long)hd*N*OO + o;
        for (int m=ml;m<N;m+=8){
            float hv = hpb[(long long)m*OO];
            #pragma unroll
            for (int r=0;r<8;r++) acc[r] = fmaf(p[r*N+m], hv, acc[r]);
        }
        #pragma unroll
        for (int r=0;r<8;r++) red2[r*256+tid]=acc[r];
        __syncthreads();
        const int rr = tid>>5;
        const int n = n0+rr;
        float v = 0.f;
        #pragma unroll
        for (int m2=0;m2<8;m2++) v += red2[rr*256 + m2*32 + o];
        if (n < N){
            v = v*sinv[rr] + bias[o];
            if (SEL==0){
                g_h1wp[(long long)(NW+n)*FF + hd*OO + o] = (v>0.f) ? v : expm1f(v);
            } else if (n < NW){
                g_out2[(hd*NW+n)*OO + o] = v;
            }
        }
    }
}

// -------- mean over heads for h2_word --------
__global__ void k_mean(){
    int i = blockIdx.x*blockDim.x + threadIdx.x;
    if (i < NW*OO){
        float s=0.f;
        #pragma unroll
        for (int h=0;h<HH;h++) s += g_out2[h*NW*OO + i];
        g_h2w[i] = s*0.125f;
    }
}

// -------- x = normalize(concat(uwa[:, :89] @ h2_word, uwa[:, 89:])) --------
// 32 rows per block (512 blocks): h2w loaded once per block instead of per row.
__global__ void __launch_bounds__(256) k_x2(const float* __restrict__ uwa,
                                            float* __restrict__ xout)
{
    extern __shared__ float sm[];
    float* su   = sm;              // [32][320]
    float* sh2  = sm + 32*320;     // [89][32]
    float* sxm  = sh2 + NW*OO;     // [32][32]
    float* srow = sxm + 1024;      // [32] reciprocal row sums

    const int b0 = blockIdx.x*32;
    const int tid = threadIdx.x;

    for (int i=tid;i<NW*OO;i+=256) sh2[i]=g_h2w[i];
    for (int i=tid;i<32*UWD;i+=256){
        int r=i/UWD, w=i-r*UWD;
        su[r*320+w]=uwa[(long long)(b0+r)*UWD + w];
    }
    __syncthreads();

    const int o = tid&31, rg = tid>>5;
    float acc[4]={0.f,0.f,0.f,0.f};
    for (int w=0;w<NW;w++){
        float hv = sh2[w*32+o];
        #pragma unroll
        for (int q=0;q<4;q++) acc[q]=fmaf(su[(rg*4+q)*320+w], hv, acc[q]);
    }
    float ts[4]={0.f,0.f,0.f,0.f};
    for (int w=NW+o; w<UWD; w+=32){
        #pragma unroll
        for (int q=0;q<4;q++) ts[q]+=su[(rg*4+q)*320+w];
    }
    #pragma unroll
    for (int q=0;q<4;q++){
        sxm[(rg*4+q)*32+o]=acc[q];
        float s = acc[q]+ts[q];
        #pragma unroll
        for (int off=16;off;off>>=1) s += __shfl_xor_sync(0xffffffffu,s,off);
        if (o==0) srow[rg*4+q]=1.f/s;
    }
    __syncthreads();
    for (int i=tid;i<32*256;i+=256){
        int r=i>>8, c=i&255;
        float v = (c<32) ? sxm[r*32+c] : su[r*320 + 57 + c];
        xout[(long long)(b0+r)*256 + c] = v*srow[r];
    }
}

// -------- dense head: output1/2, output1_new/2_new, x_temp --------
__global__ void __launch_bounds__(128) k_dense(
    const float* __restrict__ xin, const float* __restrict__ sent,
    const float* __restrict__ Ws1, const float* __restrict__ bs1,
    const float* __restrict__ Ws2, const float* __restrict__ bs2,
    const float* __restrict__ Wf1, const float* __restrict__ bf1,
    const float* __restrict__ Wfa, const float* __restrict__ bfa,
    const float* __restrict__ Wfb, const float* __restrict__ bfb,
    float* __restrict__ o1n, float* __restrict__ o2n, float* __restrict__ xt)
{
    __shared__ float so1[32*128];   // [j][r] col-major
    __shared__ float so2[32*128];
    __shared__ float buf[4096];     // k-tiles (64x36) then relu(t) [j][r]
    const int b0 = blockIdx.x*32;
    const int tid = threadIdx.x;
    float acc[32];

    // output2 = sent @ Ws2 + bs2
    #pragma unroll
    for (int r=0;r<32;r++) acc[r]=0.f;
    for (int k0=0;k0<EE2;k0+=64){
        __syncthreads();
        for (int i=tid;i<2048;i+=128){
            int r=i>>6, kk=i&63;
            buf[kk*36+r] = sent[(long long)(b0+r)*EE2 + (k0+kk)];
        }
        __syncthreads();
        #pragma unroll 2
        for (int kk=0;kk<64;kk++){
            float wv = Ws2[(k0+kk)*128 + tid];
            const float4* pv = reinterpret_cast<const float4*>(&buf[kk*36]);
            #pragma unroll
            for (int q=0;q<8;q++){
                float4 v = pv[q];
                acc[4*q+0]=fmaf(v.x,wv,acc[4*q+0]);
                acc[4*q+1]=fmaf(v.y,wv,acc[4*q+1]);
                acc[4*q+2]=fmaf(v.z,wv,acc[4*q+2]);
                acc[4*q+3]=fmaf(v.w,wv,acc[4*q+3]);
            }
        }
    }
    {
        float bb = bs2[tid];
        #pragma unroll
        for (int r=0;r<32;r++) so2[tid*32+r] = acc[r]+bb;
    }

    // output1 = x @ Ws1 + bs1
    #pragma unroll
    for (int r=0;r<32;r++) acc[r]=0.f;
    for (int k0=0;k0<256;k0+=64){
        __syncthreads();
        for (int i=tid;i<2048;i+=128){
            int r=i>>6, kk=i&63;
            buf[kk*36+r] = xin[(long long)(b0+r)*256 + (k0+kk)];
        }
        __syncthreads();
        #pragma unroll 2
        for (int kk=0;kk<64;kk++){
            float wv = Ws1[(k0+kk)*128 + tid];
            const float4* pv = reinterpret_cast<const float4*>(&buf[kk*36]);
            #pragma unroll
            for (int q=0;q<8;q++){
                float4 v = pv[q];
                acc[4*q+0]=fmaf(v.x,wv,acc[4*q+0]);
                acc[4*q+1]=fmaf(v.y,wv,acc[4*q+1]);
                acc[4*q+2]=fmaf(v.z,wv,acc[4*q+2]);
                acc[4*q+3]=fmaf(v.w,wv,acc[4*q+3]);
            }
        }
    }
    {
        float bb = bs1[tid];
        #pragma unroll
        for (int r=0;r<32;r++) so1[tid*32+r] = acc[r]+bb;
    }
    __syncthreads();

    // o1n = output1 @ Wf1 + bf1 ; o2n = output2 @ Wf1 + bf1
    {
        const int j2 = tid & 63;
        const int half = tid >> 6;
        float a1[16], a2[16];
        #pragma unroll
        for (int q=0;q<16;q++){ a1[q]=0.f; a2[q]=0.f; }
        for (int k=0;k<128;k++){
            float wv = Wf1[k*64+j2];
            const float4* p1 = reinterpret_cast<const float4*>(&so1[k*32 + half*16]);
            const float4* p2 = reinterpret_cast<const float4*>(&so2[k*32 + half*16]);
            #pragma unroll
            for (int q=0;q<4;q++){
                float4 v1=p1[q], v2=p2[q];
                a1[4*q+0]=fmaf(v1.x,wv,a1[4*q+0]); a2[4*q+0]=fmaf(v2.x,wv,a2[4*q+0]);
                a1[4*q+1]=fmaf(v1.y,wv,a1[4*q+1]); a2[4*q+1]=fmaf(v2.y,wv,a2[4*q+1]);
                a1[4*q+2]=fmaf(v1.z,wv,a1[4*q+2]); a2[4*q+2]=fmaf(v2.z,wv,a2[4*q+2]);
                a1[4*q+3]=fmaf(v1.w,wv,a1[4*q+3]); a2[4*q+3]=fmaf(v2.w,wv,a2[4*q+3]);
            }
        }
        float bb = bf1[j2];
        #pragma unroll
        for (int q=0;q<16;q++){
            int r = half*16+q;
            o1n[(long long)(b0+r)*64 + j2] = a1[q]+bb;
            o2n[(long long)(b0+r)*64 + j2] = a2[q]+bb;
        }
    }

    // t = relu(concat(output1,output2) @ Wfa + bfa)
    #pragma unroll
    for (int r=0;r<32;r++) acc[r]=0.f;
    for (int k=0;k<128;k++){
        float wv = Wfa[k*128+tid];
        const float4* pv = reinterpret_cast<const float4*>(&so1[k*32]);
        #pragma unroll
        for (int q=0;q<8;q++){
            float4 v = pv[q];
            acc[4*q+0]=fmaf(v.x,wv,acc[4*q+0]);
            acc[4*q+1]=fmaf(v.y,wv,acc[4*q+1]);
            acc[4*q+2]=fmaf(v.z,wv,acc[4*q+2]);
            acc[4*q+3]=fmaf(v.w,wv,acc[4*q+3]);
        }
    }
    for (int k=0;k<128;k++){
        float wv = Wfa[(128+k)*128+tid];
        const float4* pv = reinterpret_cast<const float4*>(&so2[k*32]);
        #pragma unroll
        for (int q=0;q<8;q++){
            float4 v = pv[q];
            acc[4*q+0]=fmaf(v.x,wv,acc[4*q+0]);
            acc[4*q+1]=fmaf(v.y,wv,acc[4*q+1]);
            acc[4*q+2]=fmaf(v.z,wv,acc[4*q+2]);
            acc[4*q+3]=fmaf(v.w,wv,acc[4*q+3]);
        }
    }
    __syncthreads();
    {
        float bb = bfa[tid];
        float4* stp = reinterpret_cast<float4*>(&buf[tid*32]);
        #pragma unroll
        for (int q=0;q<8;q++){
            float4 v;
            v.x = fmaxf(acc[4*q+0]+bb, 0.f);
            v.y = fmaxf(acc[4*q+1]+bb, 0.f);
            v.z = fmaxf(acc[4*q+2]+bb, 0.f);
            v.w = fmaxf(acc[4*q+3]+bb, 0.f);
            stp[q]=v;
        }
    }
    __syncthreads();
    // x_temp = t @ Wfb + bfb
    for (int i=tid;i<160;i+=128){
        int r=i/5, c=i%5;
        float s = bfb[c];
        for (int j=0;j<128;j++) s = fmaf(buf[j*32+r], Wfb[j*5+c], s);
        xt[(long long)(b0+r)*5 + c] = s;
    }
}

extern "C" void kernel_launch(void* const* d_in, const int* in_sizes, int n_in,
                              void* d_out, int out_size)
{
    (void)in_sizes; (void)n_in; (void)out_size;
    const float* pern  = (const float*)d_in[0];
    const float* wordf = (const float*)d_in[1];
    const int*   padj  = (const int*)d_in[2];
    const int*   wpadj = (const int*)d_in[3];
    const float* uwa   = (const float*)d_in[4];
    const float* sent  = (const float*)d_in[5];
    const float* w1    = (const float*)d_in[6];
    const float* as1   = (const float*)d_in[7];
    const float* ad1   = (const float*)d_in[8];
    const float* b1    = (const float*)d_in[9];
    const float* w2    = (const float*)d_in[10];
    const float* as2   = (const float*)d_in[11];
    const float* ad2   = (const float*)d_in[12];
    const float* b2    = (const float*)d_in[13];
    const float* Ws1   = (const float*)d_in[14];
    const float* bs1   = (const float*)d_in[15];
    const float* Ws2   = (const float*)d_in[16];
    const float* bs2   = (const float*)d_in[17];
    const float* Wf1   = (const float*)d_in[18];
    const float* bf1   = (const float*)d_in[19];
    const float* Wfa   = (const float*)d_in[20];
    const float* bfa   = (const float*)d_in[21];
    const float* Wfb   = (const float*)d_in[22];
    const float* bfb   = (const float*)d_in[23];
    float* out = (float*)d_out;

    cudaFuncSetAttribute(k_hp<0>,  cudaFuncAttributeMaxDynamicSharedMemorySize, 65536);
    cudaFuncSetAttribute(k_hp<1>,  cudaFuncAttributeMaxDynamicSharedMemorySize, 65536);
    cudaFuncSetAttribute(k_attn<0>,cudaFuncAttributeMaxDynamicSharedMemorySize, 8*NP*4);
    cudaFuncSetAttribute(k_attn<1>,cudaFuncAttributeMaxDynamicSharedMemorySize, 8*NA*4);
    cudaFuncSetAttribute(k_x2,     cudaFuncAttributeMaxDynamicSharedMemorySize, 60000);

    k_copy_word<<<(NW*FF+255)/256, 256>>>(wordf);
    k_hp<0><<<dim3(NP/32, HH), 256, 65536>>>(pern, w1, as1, ad1);
    k_attn<0><<<dim3(HH, NP/8), 256, 8*NP*4>>>(padj, out+OFF_APP, b1);
    k_hp<1><<<dim3((NA+31)/32, HH), 256, 65536>>>(pern, w2, as2, ad2);
    k_attn<1><<<dim3(HH, (NA+7)/8), 256, 8*NA*4>>>(wpadj, out+OFF_AWP, b2);
    k_mean<<<(NW*OO+255)/256, 256>>>();
    k_x2<<<BB/32, 256, (32*320 + NW*OO + 1024 + 32)*4>>>(uwa, out+OFF_X);
    k_dense<<<BB/32, 128>>>(out+OFF_X, sent, Ws1,bs1,Ws2,bs2,Wf1,bf1,Wfa,bfa,Wfb,bfb,
                            out+OFF_O1N, out+OFF_O2N, out+OFF_XT);
}

// round 8
// speedup vs baseline: 1.3878x; 1.0045x over previous
#include <cuda_runtime.h>
#include <math.h>

#define NP 2048
#define NW 89
#define NA 2137
#define BB 16384
#define EE2 768
#define UWD 313
#define HH 8
#define FF 256
#define OO 32

// output layout: concat of flattened outputs in reference return order
#define OFF_O1N 0LL                 // (B,64)
#define OFF_O2N 1048576LL           // (B,64)
#define OFF_XT  2097152LL           // (B,5)
#define OFF_APP 2179072LL           // (8,2048,2048)
#define OFF_AWP 35733504LL          // (8,2137,2137)
#define OFF_X   72267656LL          // (B,256)

// -------- scratch (no allocations allowed -> device globals) --------
__device__ float g_hp1[HH*NP*OO];
__device__ float g_es1[HH*NP];
__device__ float g_ed1[HH*NP];
__device__ float g_h1wp[NA*FF];
__device__ float g_hp2[HH*NA*OO];
__device__ float g_es2[HH*NA];
__device__ float g_ed2[HH*NA];
__device__ float g_out2[HH*NW*OO];
__device__ float g_h2w[NW*OO];

// -------- copy word features into top of h1_wp --------
__global__ void k_copy_word(const float* __restrict__ wf){
    int i = blockIdx.x*blockDim.x + threadIdx.x;
    if (i < NW*FF) g_h1wp[i] = wf[i];
}

// -------- hp = einsum('nf,hfo->hno'), plus e_src/e_dst --------
// one block = (32 rows, 1 head). 256 threads = 32 cols x 8 row-groups, 4 rows/thread.
template<int SEL>
__global__ void __launch_bounds__(256) k_hp(const float* __restrict__ hin,
        const float* __restrict__ w, const float* __restrict__ asrc,
        const float* __restrict__ adst)
{
    constexpr int N = SEL ? NA : NP;
    const float* h  = SEL ? g_h1wp : hin;
    float* hp = SEL ? g_hp2 : g_hp1;
    float* es = SEL ? g_es2 : g_es1;
    float* ed = SEL ? g_ed2 : g_ed1;

    extern __shared__ float sm[];
    float* sw = sm;          // [256][32] this head's weight slice
    float* sh = sm + 8192;   // [32][256] row tile

    const int hd = blockIdx.y;
    const int b0 = blockIdx.x*32;
    const int tid = threadIdx.x;

    {
        const float4* src = reinterpret_cast<const float4*>(w + hd*FF*OO);
        float4* dst = reinterpret_cast<float4*>(sw);
        #pragma unroll
        for (int i=0;i<8;i++) dst[tid + i*256] = src[tid + i*256];
    }
    for (int i=tid;i<2048;i+=256){
        int r=i>>6, c4=i&63;
        int n=b0+r;
        float4 v = make_float4(0.f,0.f,0.f,0.f);
        if (n<N) v = *reinterpret_cast<const float4*>(h + (long long)n*FF + c4*4);
        *reinterpret_cast<float4*>(&sh[r*256 + c4*4]) = v;
    }
    __syncthreads();

    const int o = tid&31, rg = tid>>5;
    float acc[4] = {0.f,0.f,0.f,0.f};
    const float* shr = sh + rg*4*256;
    #pragma unroll 2
    for (int k0=0;k0<256;k0+=4){
        float w0=sw[(k0+0)*32+o], w1=sw[(k0+1)*32+o];
        float w2=sw[(k0+2)*32+o], w3=sw[(k0+3)*32+o];
        #pragma unroll
        for (int q=0;q<4;q++){
            float4 hv = *reinterpret_cast<const float4*>(&shr[q*256+k0]);
            acc[q]=fmaf(hv.x,w0,acc[q]);
            acc[q]=fmaf(hv.y,w1,acc[q]);
            acc[q]=fmaf(hv.z,w2,acc[q]);
            acc[q]=fmaf(hv.w,w3,acc[q]);
        }
    }
    float av = asrc[hd*32+o];
    float dv = adst[hd*32+o];
    #pragma unroll
    for (int q=0;q<4;q++){
        int n=b0+rg*4+q;
        if (n<N) hp[((long long)hd*N+n)*OO+o]=acc[q];
        float s=acc[q]*av, d=acc[q]*dv;
        #pragma unroll
        for (int off=16;off;off>>=1){
            s+=__shfl_xor_sync(0xffffffffu,s,off);
            d+=__shfl_xor_sync(0xffffffffu,d,off);
        }
        if (o==0 && n<N){ es[hd*N+n]=s; ed[hd*N+n]=d; }
    }
}

// -------- attention: softmax rows + fused attn@hp --------
// grid = (heads, rowgroups): the 8 heads of one rowgroup are ADJACENT block ids
// so the adjacency rows are fetched from DRAM once and hit L2 for the other 7.
template<int SEL>
__global__ void __launch_bounds__(256) k_attn(const int* __restrict__ adj,
        float* __restrict__ attn, const float* __restrict__ bias)
{
    constexpr int N = SEL ? NA : NP;
    const float* hp = SEL ? g_hp2 : g_hp1;
    const float* es = SEL ? g_es2 : g_es1;
    const float* ed = SEL ? g_ed2 : g_ed1;

    extern __shared__ float p[];            // 8*N floats
    __shared__ float red[8];
    __shared__ float sinv[8];
    __shared__ float red2[2048];

    const int hd = blockIdx.x;
    const int n0 = blockIdx.y*8;
    const int tid = threadIdx.x;
    const float* edr = ed + hd*N;

    for (int r=0;r<8;r++){
        int n = n0+r;
        if (n>=N) break;                    // uniform across block
        float esn = es[hd*N+n];
        const int* arow = adj + (long long)n*N;
        float* pr = p + r*N;
        float mx = -3.0e38f;
        for (int m=tid;m<N;m+=256){
            float v = esn + edr[m];
            v = v>0.f ? v : 0.2f*v;         // leaky_relu 0.2
            if (arow[m]==0) v = -1.0e9f;
            pr[m]=v;
            mx = fmaxf(mx,v);
        }
        #pragma unroll
        for (int off=16;off;off>>=1) mx = fmaxf(mx,__shfl_xor_sync(0xffffffffu,mx,off));
        if ((tid&31)==0) red[tid>>5]=mx;
        __syncthreads();
        if (tid==0){
            float v=red[0];
            #pragma unroll
            for (int i=1;i<8;i++) v=fmaxf(v,red[i]);
            red[0]=v;
        }
        __syncthreads();
        float Mx = red[0];
        float sm = 0.f;
        for (int m=tid;m<N;m+=256){
            float q = __expf(pr[m]-Mx);
            pr[m]=q;
            sm+=q;
        }
        __syncthreads();
        #pragma unroll
        for (int off=16;off;off>>=1) sm += __shfl_xor_sync(0xffffffffu,sm,off);
        if ((tid&31)==0) red[tid>>5]=sm;
        __syncthreads();
        if (tid==0){
            float v=0.f;
            #pragma unroll
            for (int i=0;i<8;i++) v+=red[i];
            sinv[r]=1.f/v;
        }
        __syncthreads();
        float iv = sinv[r];
        float* ar = attn + ((long long)(hd*N+n))*N;
        for (int m=tid;m<N;m+=256) ar[m] = pr[m]*iv;
        __syncthreads();
    }

    // attn @ hp : GAT1 needs every row; GAT2 only rows n<89 (only h2_word is used)
    if (SEL==0 || n0 < NW){
        const int ml = tid>>5, o = tid&31;
        float acc[8];
        #pragma unroll
        for (int r=0;r<8;r++) acc[r]=0.f;
        const float* hpb = hp + (long long)hd*N*OO + o;
        for (int m=ml;m<N;m+=8){
            float hv = hpb[(long long)m*OO];
            #pragma unroll
            for (int r=0;r<8;r++) acc[r] = fmaf(p[r*N+m], hv, acc[r]);
        }
        #pragma unroll
        for (int r=0;r<8;r++) red2[r*256+tid]=acc[r];
        __syncthreads();
        const int rr = tid>>5;
        const int n = n0+rr;
        float v = 0.f;
        #pragma unroll
        for (int m2=0;m2<8;m2++) v += red2[rr*256 + m2*32 + o];
        if (n < N){
            v = v*sinv[rr] + bias[o];
            if (SEL==0){
                g_h1wp[(long long)(NW+n)*FF + hd*OO + o] = (v>0.f) ? v : expm1f(v);
            } else if (n < NW){
                g_out2[(hd*NW+n)*OO + o] = v;
            }
        }
    }
}

// -------- mean over heads for h2_word --------
__global__ void k_mean(){
    int i = blockIdx.x*blockDim.x + threadIdx.x;
    if (i < NW*OO){
        float s=0.f;
        #pragma unroll
        for (int h=0;h<HH;h++) s += g_out2[h*NW*OO + i];
        g_h2w[i] = s*0.125f;
    }
}

// -------- x = normalize(concat(uwa[:, :89] @ h2_word, uwa[:, 89:])) --------
// 32 rows per block (512 blocks): h2w loaded once per block instead of per row.
__global__ void __launch_bounds__(256) k_x2(const float* __restrict__ uwa,
                                            float* __restrict__ xout)
{
    extern __shared__ float sm[];
    float* su   = sm;              // [32][320]
    float* sh2  = sm + 32*320;     // [89][32]
    float* sxm  = sh2 + NW*OO;     // [32][32]
    float* srow = sxm + 1024;      // [32] reciprocal row sums

    const int b0 = blockIdx.x*32;
    const int tid = threadIdx.x;

    for (int i=tid;i<NW*OO;i+=256) sh2[i]=g_h2w[i];
    for (int i=tid;i<32*UWD;i+=256){
        int r=i/UWD, w=i-r*UWD;
        su[r*320+w]=uwa[(long long)(b0+r)*UWD + w];
    }
    __syncthreads();

    const int o = tid&31, rg = tid>>5;
    float acc[4]={0.f,0.f,0.f,0.f};
    for (int w=0;w<NW;w++){
        float hv = sh2[w*32+o];
        #pragma unroll
        for (int q=0;q<4;q++) acc[q]=fmaf(su[(rg*4+q)*320+w], hv, acc[q]);
    }
    float ts[4]={0.f,0.f,0.f,0.f};
    for (int w=NW+o; w<UWD; w+=32){
        #pragma unroll
        for (int q=0;q<4;q++) ts[q]+=su[(rg*4+q)*320+w];
    }
    #pragma unroll
    for (int q=0;q<4;q++){
        sxm[(rg*4+q)*32+o]=acc[q];
        float s = acc[q]+ts[q];
        #pragma unroll
        for (int off=16;off;off>>=1) s += __shfl_xor_sync(0xffffffffu,s,off);
        if (o==0) srow[rg*4+q]=1.f/s;
    }
    __syncthreads();
    for (int i=tid;i<32*256;i+=256){
        int r=i>>8, c=i&255;
        float v = (c<32) ? sxm[r*32+c] : su[r*320 + 57 + c];
        xout[(long long)(b0+r)*256 + c] = v*srow[r];
    }
}

// -------- dense head: output1/2, output1_new/2_new, x_temp --------
__global__ void __launch_bounds__(128) k_dense(
    const float* __restrict__ xin, const float* __restrict__ sent,
    const float* __restrict__ Ws1, const float* __restrict__ bs1,
    const float* __restrict__ Ws2, const float* __restrict__ bs2,
    const float* __restrict__ Wf1, const float* __restrict__ bf1,
    const float* __restrict__ Wfa, const float* __restrict__ bfa,
    const float* __restrict__ Wfb, const float* __restrict__ bfb,
    float* __restrict__ o1n, float* __restrict__ o2n, float* __restrict__ xt)
{
    __shared__ float so1[32*128];   // [j][r] col-major
    __shared__ float so2[32*128];
    __shared__ float buf[4096];     // k-tiles (64x36) then relu(t) [j][r]
    const int b0 = blockIdx.x*32;
    const int tid = threadIdx.x;
    float acc[32];

    // output2 = sent @ Ws2 + bs2
    #pragma unroll
    for (int r=0;r<32;r++) acc[r]=0.f;
    for (int k0=0;k0<EE2;k0+=64){
        __syncthreads();
        for (int i=tid;i<2048;i+=128){
            int r=i>>6, kk=i&63;
            buf[kk*36+r] = sent[(long long)(b0+r)*EE2 + (k0+kk)];
        }
        __syncthreads();
        #pragma unroll 2
        for (int kk=0;kk<64;kk++){
            float wv = Ws2[(k0+kk)*128 + tid];
            const float4* pv = reinterpret_cast<const float4*>(&buf[kk*36]);
            #pragma unroll
            for (int q=0;q<8;q++){
                float4 v = pv[q];
                acc[4*q+0]=fmaf(v.x,wv,acc[4*q+0]);
                acc[4*q+1]=fmaf(v.y,wv,acc[4*q+1]);
                acc[4*q+2]=fmaf(v.z,wv,acc[4*q+2]);
                acc[4*q+3]=fmaf(v.w,wv,acc[4*q+3]);
            }
        }
    }
    {
        float bb = bs2[tid];
        #pragma unroll
        for (int r=0;r<32;r++) so2[tid*32+r] = acc[r]+bb;
    }

    // output1 = x @ Ws1 + bs1
    #pragma unroll
    for (int r=0;r<32;r++) acc[r]=0.f;
    for (int k0=0;k0<256;k0+=64){
        __syncthreads();
        for (int i=tid;i<2048;i+=128){
            int r=i>>6, kk=i&63;
            buf[kk*36+r] = xin[(long long)(b0+r)*256 + (k0+kk)];
        }
        __syncthreads();
        #pragma unroll 2
        for (int kk=0;kk<64;kk++){
            float wv = Ws1[(k0+kk)*128 + tid];
            const float4* pv = reinterpret_cast<const float4*>(&buf[kk*36]);
            #pragma unroll
            for (int q=0;q<8;q++){
                float4 v = pv[q];
                acc[4*q+0]=fmaf(v.x,wv,acc[4*q+0]);
                acc[4*q+1]=fmaf(v.y,wv,acc[4*q+1]);
                acc[4*q+2]=fmaf(v.z,wv,acc[4*q+2]);
                acc[4*q+3]=fmaf(v.w,wv,acc[4*q+3]);
            }
        }
    }
    {
        float bb = bs1[tid];
        #pragma unroll
        for (int r=0;r<32;r++) so1[tid*32+r] = acc[r]+bb;
    }
    __syncthreads();

    // o1n = output1 @ Wf1 + bf1 ; o2n = output2 @ Wf1 + bf1
    {
        const int j2 = tid & 63;
        const int half = tid >> 6;
        float a1[16], a2[16];
        #pragma unroll
        for (int q=0;q<16;q++){ a1[q]=0.f; a2[q]=0.f; }
        for (int k=0;k<128;k++){
            float wv = Wf1[k*64+j2];
            const float4* p1 = reinterpret_cast<const float4*>(&so1[k*32 + half*16]);
            const float4* p2 = reinterpret_cast<const float4*>(&so2[k*32 + half*16]);
            #pragma unroll
            for (int q=0;q<4;q++){
                float4 v1=p1[q], v2=p2[q];
                a1[4*q+0]=fmaf(v1.x,wv,a1[4*q+0]); a2[4*q+0]=fmaf(v2.x,wv,a2[4*q+0]);
                a1[4*q+1]=fmaf(v1.y,wv,a1[4*q+1]); a2[4*q+1]=fmaf(v2.y,wv,a2[4*q+1]);
                a1[4*q+2]=fmaf(v1.z,wv,a1[4*q+2]); a2[4*q+2]=fmaf(v2.z,wv,a2[4*q+2]);
                a1[4*q+3]=fmaf(v1.w,wv,a1[4*q+3]); a2[4*q+3]=fmaf(v2.w,wv,a2[4*q+3]);
            }
        }
        float bb = bf1[j2];
        #pragma unroll
        for (int q=0;q<16;q++){
            int r = half*16+q;
            o1n[(long long)(b0+r)*64 + j2] = a1[q]+bb;
            o2n[(long long)(b0+r)*64 + j2] = a2[q]+bb;
        }
    }

    // t = relu(concat(output1,output2) @ Wfa + bfa)
    #pragma unroll
    for (int r=0;r<32;r++) acc[r]=0.f;
    for (int k=0;k<128;k++){
        float wv = Wfa[k*128+tid];
        const float4* pv = reinterpret_cast<const float4*>(&so1[k*32]);
        #pragma unroll
        for (int q=0;q<8;q++){
            float4 v = pv[q];
            acc[4*q+0]=fmaf(v.x,wv,acc[4*q+0]);
            acc[4*q+1]=fmaf(v.y,wv,acc[4*q+1]);
            acc[4*q+2]=fmaf(v.z,wv,acc[4*q+2]);
            acc[4*q+3]=fmaf(v.w,wv,acc[4*q+3]);
        }
    }
    for (int k=0;k<128;k++){
        float wv = Wfa[(128+k)*128+tid];
        const float4* pv = reinterpret_cast<const float4*>(&so2[k*32]);
        #pragma unroll
        for (int q=0;q<8;q++){
            float4 v = pv[q];
            acc[4*q+0]=fmaf(v.x,wv,acc[4*q+0]);
            acc[4*q+1]=fmaf(v.y,wv,acc[4*q+1]);
            acc[4*q+2]=fmaf(v.z,wv,acc[4*q+2]);
            acc[4*q+3]=fmaf(v.w,wv,acc[4*q+3]);
        }
    }
    __syncthreads();
    {
        float bb = bfa[tid];
        float4* stp = reinterpret_cast<float4*>(&buf[tid*32]);
        #pragma unroll
        for (int q=0;q<8;q++){
            float4 v;
            v.x = fmaxf(acc[4*q+0]+bb, 0.f);
            v.y = fmaxf(acc[4*q+1]+bb, 0.f);
            v.z = fmaxf(acc[4*q+2]+bb, 0.f);
            v.w = fmaxf(acc[4*q+3]+bb, 0.f);
            stp[q]=v;
        }
    }
    __syncthreads();
    // x_temp = t @ Wfb + bfb
    for (int i=tid;i<160;i+=128){
        int r=i/5, c=i%5;
        float s = bfb[c];
        for (int j=0;j<128;j++) s = fmaf(buf[j*32+r], Wfb[j*5+c], s);
        xt[(long long)(b0+r)*5 + c] = s;
    }
}

extern "C" void kernel_launch(void* const* d_in, const int* in_sizes, int n_in,
                              void* d_out, int out_size)
{
    (void)in_sizes; (void)n_in; (void)out_size;
    const float* pern  = (const float*)d_in[0];
    const float* wordf = (const float*)d_in[1];
    const int*   padj  = (const int*)d_in[2];
    const int*   wpadj = (const int*)d_in[3];
    const float* uwa   = (const float*)d_in[4];
    const float* sent  = (const float*)d_in[5];
    const float* w1    = (const float*)d_in[6];
    const float* as1   = (const float*)d_in[7];
    const float* ad1   = (const float*)d_in[8];
    const float* b1    = (const float*)d_in[9];
    const float* w2    = (const float*)d_in[10];
    const float* as2   = (const float*)d_in[11];
    const float* ad2   = (const float*)d_in[12];
    const float* b2    = (const float*)d_in[13];
    const float* Ws1   = (const float*)d_in[14];
    const float* bs1   = (const float*)d_in[15];
    const float* Ws2   = (const float*)d_in[16];
    const float* bs2   = (const float*)d_in[17];
    const float* Wf1   = (const float*)d_in[18];
    const float* bf1   = (const float*)d_in[19];
    const float* Wfa   = (const float*)d_in[20];
    const float* bfa   = (const float*)d_in[21];
    const float* Wfb   = (const float*)d_in[22];
    const float* bfb   = (const float*)d_in[23];
    float* out = (float*)d_out;

    cudaFuncSetAttribute(k_hp<0>,  cudaFuncAttributeMaxDynamicSharedMemorySize, 65536);
    cudaFuncSetAttribute(k_hp<1>,  cudaFuncAttributeMaxDynamicSharedMemorySize, 65536);
    cudaFuncSetAttribute(k_attn<0>,cudaFuncAttributeMaxDynamicSharedMemorySize, 8*NP*4);
    cudaFuncSetAttribute(k_attn<1>,cudaFuncAttributeMaxDynamicSharedMemorySize, 8*NA*4);
    cudaFuncSetAttribute(k_x2,     cudaFuncAttributeMaxDynamicSharedMemorySize, 60000);

    k_copy_word<<<(NW*FF+255)/256, 256>>>(wordf);
    k_hp<0><<<dim3(NP/32, HH), 256, 65536>>>(pern, w1, as1, ad1);
    k_attn<0><<<dim3(HH, NP/8), 256, 8*NP*4>>>(padj, out+OFF_APP, b1);
    k_hp<1><<<dim3((NA+31)/32, HH), 256, 65536>>>(pern, w2, as2, ad2);
    k_attn<1><<<dim3(HH, (NA+7)/8), 256, 8*NA*4>>>(wpadj, out+OFF_AWP, b2);
    k_mean<<<(NW*OO+255)/256, 256>>>();
    k_x2<<<BB/32, 256, (32*320 + NW*OO + 1024 + 32)*4>>>(uwa, out+OFF_X);
    k_dense<<<BB/32, 128>>>(out+OFF_X, sent, Ws1,bs1,Ws2,bs2,Wf1,bf1,Wfa,bfa,Wfb,bfb,
                            out+OFF_O1N, out+OFF_O2N, out+OFF_XT);
}